// round 14
// baseline (speedup 1.0000x reference)
#include <cuda_runtime.h>
#include <cuda_bf16.h>
#include <math.h>

#define BB 2
#define SSEQ 4096
#define NH 8
#define DHEAD 64
#define HD 512
#define LM 128
#define WWIN 128
#define EXTW 64
#define HL 1024
#define NKEY 384
#define QT 32

// ---------------- scratch (device globals; no allocations) ----------------
__device__ float g_Q [BB*SSEQ*HD];
__device__ float g_K [BB*SSEQ*HD];
__device__ float g_V [BB*SSEQ*HD];
__device__ float g_Dl[BB*SSEQ*HL];   // D logits, softmaxed in-place -> hs
__device__ float g_Kc[BB*LM*HD];
__device__ float g_Vc[BB*LM*HD];

// bf16 arena: X hi/lo, C hi/lo, transposed-weight hi/lo
#define XHI  0
#define XLO  4194304
#define CHI  8388608
#define CLO  12582912
#define WQTH 16777216
#define WQTL 17039360
#define WKTH 17301504
#define WKTL 17563648
#define WVTH 17825792
#define WVTL 18087936
#define WDTH 18350080
#define WDTL 18874368
#define WOTH 19398656
#define WOTL 19660800
__device__ __nv_bfloat16 g_bf[19922944];

// ================= helpers =================
__device__ __forceinline__ unsigned smem_u32(const void* p) {
    unsigned a;
    asm("{ .reg .u64 t; cvta.to.shared.u64 t, %1; cvt.u32.u64 %0, t; }" : "=r"(a) : "l"(p));
    return a;
}
__device__ __forceinline__ unsigned swz(unsigned b) { return b ^ ((b >> 3) & 0x70u); }

__device__ __forceinline__ void ldsm_x4(unsigned* r, unsigned addr) {
    asm volatile("ldmatrix.sync.aligned.m8n8.x4.shared.b16 {%0,%1,%2,%3}, [%4];"
        : "=r"(r[0]),"=r"(r[1]),"=r"(r[2]),"=r"(r[3]) : "r"(addr));
}
__device__ __forceinline__ void ldsm_x2(unsigned* r, unsigned addr) {
    asm volatile("ldmatrix.sync.aligned.m8n8.x2.shared.b16 {%0,%1}, [%2];"
        : "=r"(r[0]),"=r"(r[1]) : "r"(addr));
}
__device__ __forceinline__ void ldsm_x2t(unsigned* r, unsigned addr) {
    asm volatile("ldmatrix.sync.aligned.m8n8.x2.trans.shared.b16 {%0,%1}, [%2];"
        : "=r"(r[0]),"=r"(r[1]) : "r"(addr));
}
__device__ __forceinline__ void mma16816(float* c, const unsigned* a, const unsigned* b) {
    asm volatile("mma.sync.aligned.m16n8k16.row.col.f32.bf16.bf16.f32 "
        "{%0,%1,%2,%3}, {%4,%5,%6,%7}, {%8,%9}, {%0,%1,%2,%3};"
        : "+f"(c[0]),"+f"(c[1]),"+f"(c[2]),"+f"(c[3])
        : "r"(a[0]),"r"(a[1]),"r"(a[2]),"r"(a[3]), "r"(b[0]),"r"(b[1]));
}
// split one float into hi/lo bf16
__device__ __forceinline__ void bsplit(float x, __nv_bfloat16& h, __nv_bfloat16& l) {
    h = __float2bfloat16(x);
    l = __float2bfloat16(x - __bfloat162float(h));
}

// ================= bf16-split conversion kernels =================
__global__ __launch_bounds__(256) void split_kernel(
    const float* __restrict__ src, __nv_bfloat16* __restrict__ hi,
    __nv_bfloat16* __restrict__ lo, int n)
{
    int i = (blockIdx.x * 256 + threadIdx.x) * 8;
    if (i >= n) return;
    #pragma unroll
    for (int j = 0; j < 8; j += 4) {
        float4 v = *(const float4*)(src + i + j);
        __nv_bfloat16 h0,h1,h2,h3,l0,l1,l2,l3;
        bsplit(v.x,h0,l0); bsplit(v.y,h1,l1); bsplit(v.z,h2,l2); bsplit(v.w,h3,l3);
        *(__nv_bfloat162*)(hi + i + j)     = __halves2bfloat162(h0, h1);
        *(__nv_bfloat162*)(hi + i + j + 2) = __halves2bfloat162(h2, h3);
        *(__nv_bfloat162*)(lo + i + j)     = __halves2bfloat162(l0, l1);
        *(__nv_bfloat162*)(lo + i + j + 2) = __halves2bfloat162(l2, l3);
    }
}

// All 5 weights transposed+split in one launch.
__global__ __launch_bounds__(256) void transpose_split_all_kernel(
    const float* __restrict__ Wq, const float* __restrict__ Wk,
    const float* __restrict__ Wv, const float* __restrict__ Wd,
    const float* __restrict__ Wo, __nv_bfloat16* __restrict__ base)
{
    __shared__ float tile[32][33];
    const int id = blockIdx.x;
    const float* W; __nv_bfloat16 *Th, *Tl; int N, tl;
    if (id < 256)       { W = Wq; Th = base+WQTH; Tl = base+WQTL; N = 512;  tl = id; }
    else if (id < 512)  { W = Wk; Th = base+WKTH; Tl = base+WKTL; N = 512;  tl = id-256; }
    else if (id < 768)  { W = Wv; Th = base+WVTH; Tl = base+WVTL; N = 512;  tl = id-512; }
    else if (id < 1280) { W = Wd; Th = base+WDTH; Tl = base+WDTL; N = 1024; tl = id-768; }
    else                { W = Wo; Th = base+WOTH; Tl = base+WOTL; N = 512;  tl = id-1280; }
    const int nt = N >> 5;
    const int n0 = (tl % nt) * 32, k0 = (tl / nt) * 32;
    const int tx = threadIdx.x, ty = threadIdx.y;
    #pragma unroll
    for (int i = 0; i < 32; i += 8)
        tile[ty + i][tx] = W[(size_t)(k0 + ty + i) * N + n0 + tx];
    __syncthreads();
    #pragma unroll
    for (int i = 0; i < 32; i += 8) {
        float x = tile[tx][ty + i];
        __nv_bfloat16 h, l; bsplit(x, h, l);
        size_t o = (size_t)(n0 + ty + i) * 512 + k0 + tx;
        Th[o] = h; Tl[o] = l;
    }
}

// ================= bf16-split GEMM core (mma.sync HMMA) =================
#define GEMM_CORE(Ahi, Alo, Bhi, Blo, Cptr, Nw, alphav, biasptr)                      \
{                                                                                      \
    float acc[4][4][4];                                                                \
    _Pragma("unroll")                                                                  \
    for (int i=0;i<4;i++) _Pragma("unroll") for (int j=0;j<4;j++)                      \
        _Pragma("unroll") for (int k=0;k<4;k++) acc[i][j][k]=0.f;                      \
    {                                                                                  \
        uint4 rg[8];                                                                   \
        _Pragma("unroll")                                                              \
        for (int i = 0; i < 4; ++i) {                                                  \
            int e = i*256 + tid; int r = e >> 3, u = e & 7;                            \
            rg[i]   = *(const uint4*)((Ahi) + (size_t)(bm*128 + r)*512 + u*8);         \
            rg[4+i] = *(const uint4*)((Bhi) + (size_t)(lbn*128 + r)*512 + u*8);        \
        }                                                                              \
        _Pragma("unroll")                                                              \
        for (int i = 0; i < 4; ++i) {                                                  \
            int e = i*256 + tid; int r = e >> 3, u = e & 7;                            \
            unsigned off = swz((unsigned)(r*128 + u*16));                              \
            *(uint4*)(smem + off)          = rg[i];                                    \
            *(uint4*)(smem + 16384u + off) = rg[4+i];                                  \
        }                                                                              \
    }                                                                                  \
    __syncthreads();                                                                   \
    for (int c = 0; c < 24; ++c) {                                                     \
        uint4 rn[8];                                                                   \
        if (c < 23) {                                                                  \
            const int cn = c + 1;                                                      \
            const __nv_bfloat16* As = (cn >= 16) ? (Alo) : (Ahi);                      \
            const __nv_bfloat16* Bs = (cn >= 8 && cn < 16) ? (Blo) : (Bhi);            \
            const int kc = cn & 7;                                                     \
            _Pragma("unroll")                                                          \
            for (int i = 0; i < 4; ++i) {                                              \
                int e = i*256 + tid; int r = e >> 3, u = e & 7;                        \
                rn[i]   = *(const uint4*)(As + (size_t)(bm*128 + r)*512 + kc*64 + u*8);\
                rn[4+i] = *(const uint4*)(Bs + (size_t)(lbn*128 + r)*512 + kc*64 + u*8);\
            }                                                                          \
        }                                                                              \
        gemm_compute_stage(sb, c & 1, wm, wn, lane, acc);                              \
        if (c < 23) {                                                                  \
            const unsigned basest = (unsigned)((c + 1) & 1) * 32768u;                  \
            _Pragma("unroll")                                                          \
            for (int i = 0; i < 4; ++i) {                                              \
                int e = i*256 + tid; int r = e >> 3, u = e & 7;                        \
                unsigned off = swz((unsigned)(r*128 + u*16));                          \
                *(uint4*)(smem + basest + off)          = rn[i];                       \
                *(uint4*)(smem + basest + 16384u + off) = rn[4+i];                     \
            }                                                                          \
        }                                                                              \
        __syncthreads();                                                               \
    }                                                                                  \
    _Pragma("unroll")                                                                  \
    for (int ma = 0; ma < 4; ++ma) {                                                   \
        const int row = bm*128 + wm*64 + ma*16 + (lane >> 2);                          \
        _Pragma("unroll")                                                              \
        for (int na = 0; na < 4; ++na) {                                               \
            const int col = lbn*128 + wn*32 + na*8 + (lane & 3)*2;                     \
            const float b0 = (biasptr)[col], b1 = (biasptr)[col+1];                    \
            float2 o0, o1;                                                             \
            o0.x = (alphav)*(acc[ma][na][0] + b0);                                     \
            o0.y = (alphav)*(acc[ma][na][1] + b1);                                     \
            o1.x = (alphav)*(acc[ma][na][2] + b0);                                     \
            o1.y = (alphav)*(acc[ma][na][3] + b1);                                     \
            *(float2*)((Cptr) + (size_t)row*(Nw) + col)     = o0;                      \
            *(float2*)((Cptr) + (size_t)(row+8)*(Nw) + col) = o1;                      \
        }                                                                              \
    }                                                                                  \
}

__device__ __forceinline__ void gemm_compute_stage(
    unsigned sb, int st, int wm, int wn, int lane, float acc[4][4][4])
{
    const unsigned sA = sb + (unsigned)st * 32768u;
    const unsigned sB = sA + 16384u;
    const int la = lane & 15;
    #pragma unroll
    for (int ks = 0; ks < 4; ++ks) {
        unsigned a[4][4], b[4][2];
        #pragma unroll
        for (int ma = 0; ma < 4; ++ma) {
            unsigned arow = (unsigned)(wm*64 + ma*16 + la);
            unsigned ab   = (unsigned)(ks*32 + ((lane>>4)&1)*16);
            ldsm_x4(a[ma], sA + swz(arow*128u + ab));
        }
        #pragma unroll
        for (int na = 0; na < 4; ++na) {
            unsigned brow = (unsigned)(wn*32 + na*8 + (la & 7));
            unsigned bb   = (unsigned)(ks*32 + ((la>>3)&1)*16);
            ldsm_x2(b[na], sB + swz(brow*128u + bb));
        }
        #pragma unroll
        for (int ma = 0; ma < 4; ++ma)
            #pragma unroll
            for (int na = 0; na < 4; ++na)
                mma16816(acc[ma][na], a[ma], b[na]);
    }
}

// generic single GEMM (used for the Wo projection)
__global__ __launch_bounds__(256) void gemm_mma_kernel(
    const __nv_bfloat16* __restrict__ Ahi, const __nv_bfloat16* __restrict__ Alo,
    const __nv_bfloat16* __restrict__ Bhi, const __nv_bfloat16* __restrict__ Blo,
    const float* __restrict__ bias, float* __restrict__ C, int N, float alpha)
{
    extern __shared__ __align__(128) char smem[];
    const unsigned sb = smem_u32(smem);
    const int tid  = threadIdx.x;
    const int lane = tid & 31, wid = tid >> 5;
    const int wm = wid >> 2, wn = wid & 3;
    const int bm = blockIdx.y, lbn = blockIdx.x;
    GEMM_CORE(Ahi, Alo, Bhi, Blo, C, N, alpha, bias);
}

// fused 4-projection GEMM: bn 0-3 Q, 4-7 K, 8-11 V, 12-19 D-logits
__global__ __launch_bounds__(256) void proj4_kernel(
    const __nv_bfloat16* __restrict__ Ahi, const __nv_bfloat16* __restrict__ Alo,
    const __nv_bfloat16* __restrict__ Qh, const __nv_bfloat16* __restrict__ Ql,
    const __nv_bfloat16* __restrict__ Kh, const __nv_bfloat16* __restrict__ Kl,
    const __nv_bfloat16* __restrict__ Vh, const __nv_bfloat16* __restrict__ Vl,
    const __nv_bfloat16* __restrict__ Dh, const __nv_bfloat16* __restrict__ Dlw,
    const float* __restrict__ bq, const float* __restrict__ bk,
    const float* __restrict__ bv, const float* __restrict__ bd,
    float* __restrict__ oQ, float* __restrict__ oK,
    float* __restrict__ oV, float* __restrict__ oD)
{
    extern __shared__ __align__(128) char smem[];
    const unsigned sb = smem_u32(smem);
    const int tid  = threadIdx.x;
    const int lane = tid & 31, wid = tid >> 5;
    const int wm = wid >> 2, wn = wid & 3;
    const int bm = blockIdx.y;
    const int bn = blockIdx.x;

    const __nv_bfloat16 *Bh, *Bl; const float* bias; float* Cp;
    int lbn, N; float alpha = 1.f;
    if (bn < 4)       { lbn = bn;    Bh = Qh; Bl = Ql;  bias = bq; Cp = oQ; N = 512; alpha = 0.125f; }
    else if (bn < 8)  { lbn = bn-4;  Bh = Kh; Bl = Kl;  bias = bk; Cp = oK; N = 512; }
    else if (bn < 12) { lbn = bn-8;  Bh = Vh; Bl = Vl;  bias = bv; Cp = oV; N = 512; }
    else              { lbn = bn-12; Bh = Dh; Bl = Dlw; bias = bd; Cp = oD; N = 1024; }
    GEMM_CORE(Ahi, Alo, Bh, Bl, Cp, N, alpha, bias);
}

// ---------------- LayerNorm over rows of 512, two tensors in one launch ----------------
__global__ __launch_bounds__(128) void ln512x2_kernel(
    float* __restrict__ Y1, float* __restrict__ Y2, int M1,
    const float* __restrict__ gam, const float* __restrict__ bet)
{
    const int row = blockIdx.x;
    float* x = (row < M1) ? (Y1 + (size_t)row * HD) : (Y2 + (size_t)(row - M1) * HD);
    const int t = threadIdx.x;
    float4 v = *(float4*)(x + t*4);
    float s  = v.x+v.y+v.z+v.w;
    float ss = v.x*v.x + v.y*v.y + v.z*v.z + v.w*v.w;
    #pragma unroll
    for (int o=16;o>0;o>>=1) {
        s  += __shfl_xor_sync(0xffffffffu, s, o);
        ss += __shfl_xor_sync(0xffffffffu, ss, o);
    }
    __shared__ float rs[4], rss[4];
    if ((t&31)==0) { rs[t>>5]=s; rss[t>>5]=ss; }
    __syncthreads();
    s  = rs[0]+rs[1]+rs[2]+rs[3];
    ss = rss[0]+rss[1]+rss[2]+rss[3];
    const float mean = s * (1.f/HD);
    const float var  = ss*(1.f/HD) - mean*mean;
    const float inv  = rsqrtf(var + 1e-5f);
    float4 g4 = *(const float4*)(gam + t*4);
    float4 b4 = *(const float4*)(bet + t*4);
    v.x = (v.x-mean)*inv*g4.x + b4.x;
    v.y = (v.y-mean)*inv*g4.y + b4.y;
    v.z = (v.z-mean)*inv*g4.z + b4.z;
    v.w = (v.w-mean)*inv*g4.w + b4.w;
    *(float4*)(x + t*4) = v;
}

// ---------------- softmax over sequence axis of g_Dl (B,S,HL), in-place ----------------
__global__ void softmax_seq_kernel()
{
    const int b = blockIdx.y;
    const int j = blockIdx.x*32 + threadIdx.x;
    const int ty = threadIdx.y;
    float m = -3.0e38f;
    for (int s = ty; s < SSEQ; s += 32)
        m = fmaxf(m, g_Dl[(size_t)(b*SSEQ+s)*HL + j]);
    __shared__ float sM[32][33];
    __shared__ float sS[32][33];
    sM[ty][threadIdx.x] = m;
    __syncthreads();
    float M = -3.0e38f;
    #pragma unroll
    for (int i=0;i<32;i++) M = fmaxf(M, sM[i][threadIdx.x]);
    float ssum = 0.f;
    for (int s = ty; s < SSEQ; s += 32)
        ssum += __expf(g_Dl[(size_t)(b*SSEQ+s)*HL + j] - M);
    sS[ty][threadIdx.x] = ssum;
    __syncthreads();
    float tot = 0.f;
    #pragma unroll
    for (int i=0;i<32;i++) tot += sS[i][threadIdx.x];
    const float inv = 1.f / tot;
    for (int s = ty; s < SSEQ; s += 32) {
        size_t off = (size_t)(b*SSEQ+s)*HL + j;
        g_Dl[off] = __expf(g_Dl[off] - M) * inv;
    }
}

// ---------------- zero Kc/Vc ----------------
__global__ void zero_kv_kernel()
{
    int i = blockIdx.x*256 + threadIdx.x;
    if (i < BB*LM*HD) { g_Kc[i]=0.f; g_Vc[i]=0.f; }
}

// ---------------- Kc = hs^T @ K, Vc = hs^T @ V (per b,h), split-K=8 with atomics ----------------
__global__ __launch_bounds__(256) void landmark_kv_kernel()
{
    const int b = blockIdx.x >> 3;
    const int h = blockIdx.x & 7;
    const int s0 = blockIdx.y * (SSEQ/8);
    __shared__ float sh[8][128];
    __shared__ float sk[8][64];
    __shared__ float sv[8][64];
    const int t = threadIdx.x;
    const int d  = t & 63;
    const int lg = t >> 6;
    float aK[32], aV[32];
    #pragma unroll
    for (int i=0;i<32;i++){aK[i]=0.f;aV[i]=0.f;}

    for (int sc = 0; sc < SSEQ/8; sc += 8) {
        #pragma unroll
        for (int u = 0; u < 8; ++u) {
            int idx = u*256 + t;
            int si = idx >> 8;
            int c  = idx & 255;
            int s  = s0 + sc + si;
            if (c < 128)      sh[si][c]     = g_Dl[(size_t)(b*SSEQ+s)*HL + h*LM + c];
            else if (c < 192) sk[si][c-128] = g_K [(size_t)(b*SSEQ+s)*HD + h*DHEAD + (c-128)];
            else              sv[si][c-192] = g_V [(size_t)(b*SSEQ+s)*HD + h*DHEAD + (c-192)];
        }
        __syncthreads();
        #pragma unroll
        for (int si=0; si<8; ++si) {
            const float kv = sk[si][d];
            const float vv = sv[si][d];
            const float4* hp = (const float4*)&sh[si][lg*32];
            #pragma unroll
            for (int i4=0;i4<8;i4++){
                float4 h4 = hp[i4];
                aK[i4*4+0] += h4.x*kv; aV[i4*4+0] += h4.x*vv;
                aK[i4*4+1] += h4.y*kv; aV[i4*4+1] += h4.y*vv;
                aK[i4*4+2] += h4.z*kv; aV[i4*4+2] += h4.z*vv;
                aK[i4*4+3] += h4.w*kv; aV[i4*4+3] += h4.w*vv;
            }
        }
        __syncthreads();
    }
    #pragma unroll
    for (int i=0;i<32;i++){
        const int l = lg*32 + i;
        atomicAdd(&g_Kc[(size_t)(b*LM+l)*HD + h*DHEAD + d], aK[i]);
        atomicAdd(&g_Vc[(size_t)(b*LM+l)*HD + h*DHEAD + d], aV[i]);
    }
}

// ---------------- fused attention on HMMA: QK^T + softmax + PV, bf16-split 3-term ----------------
// smem: Sc 32x385 f32 (49280 B) | Ph 4KB | Pl 4KB (Q hi/lo, reused for P) | Th 8KB | Tl 8KB
__global__ __launch_bounds__(256) void attn_kernel(
    const int* __restrict__ mask,
    __nv_bfloat16* __restrict__ Chi, __nv_bfloat16* __restrict__ Clo)
{
    extern __shared__ __align__(128) char smem[];
    float* Sc = (float*)smem;
    char* Ph = smem + 49280;
    char* Pl = Ph + 4096;
    char* Th = Pl + 4096;
    char* Tl = Th + 8192;
    __shared__ int vld[64];

    const unsigned sb  = smem_u32(smem);
    const unsigned sPh = sb + 49280u, sPl = sPh + 4096u;
    const unsigned sTh = sPl + 4096u, sTl = sTh + 8192u;

    const int b  = blockIdx.z;
    const int h  = blockIdx.y;
    const int q0 = blockIdx.x * QT;
    const int g  = q0 >> 7;
    const int t  = threadIdx.x;
    const int lane = t & 31, wn = t >> 5;
    const int la = lane & 15;

    // ---- Q (32x64 fp32) -> bf16 hi/lo swizzled smem ----
    #pragma unroll
    for (int u = 0; u < 2; ++u) {
        int idx = u*256 + t;            // 512 float4
        int q = idx >> 4, c = idx & 15;
        float4 v = *(const float4*)&g_Q[(size_t)(b*SSEQ+q0+q)*HD + h*DHEAD + c*4];
        __nv_bfloat16 h0,h1,h2,h3,l0,l1,l2,l3;
        bsplit(v.x,h0,l0); bsplit(v.y,h1,l1); bsplit(v.z,h2,l2); bsplit(v.w,h3,l3);
        unsigned off = swz((unsigned)(q*128 + c*8));
        *(__nv_bfloat162*)(Ph+off)   = __halves2bfloat162(h0,h1);
        *(__nv_bfloat162*)(Ph+off+4) = __halves2bfloat162(h2,h3);
        *(__nv_bfloat162*)(Pl+off)   = __halves2bfloat162(l0,l1);
        *(__nv_bfloat162*)(Pl+off+4) = __halves2bfloat162(l2,l3);
    }

    // ---- score tiles ----
    for (int kt = 0; kt < 6; ++kt) {
        __syncthreads();
        if (t < 64) {
            int ok = 1;
            if (kt >= 2) {
                int p = g*WWIN - EXTW + (kt-2)*64 + t;
                ok = (p >= 0 && p < SSEQ) ? (mask[b*SSEQ+p] != 0) : 0;
            }
            vld[t] = ok;
        }
        #pragma unroll
        for (int u = 0; u < 4; ++u) {
            int idx = u*256 + t;        // 1024 float4
            int kk = idx >> 4, c = idx & 15;
            float4 v = make_float4(0.f,0.f,0.f,0.f);
            if (kt < 2) {
                v = *(const float4*)&g_Kc[(size_t)(b*LM + kt*64 + kk)*HD + h*DHEAD + c*4];
            } else {
                int p = g*WWIN - EXTW + (kt-2)*64 + kk;
                if (p >= 0 && p < SSEQ)
                    v = *(const float4*)&g_K[(size_t)(b*SSEQ+p)*HD + h*DHEAD + c*4];
            }
            __nv_bfloat16 h0,h1,h2,h3,l0,l1,l2,l3;
            bsplit(v.x,h0,l0); bsplit(v.y,h1,l1); bsplit(v.z,h2,l2); bsplit(v.w,h3,l3);
            unsigned off = swz((unsigned)(kk*128 + c*8));
            *(__nv_bfloat162*)(Th+off)   = __halves2bfloat162(h0,h1);
            *(__nv_bfloat162*)(Th+off+4) = __halves2bfloat162(h2,h3);
            *(__nv_bfloat162*)(Tl+off)   = __halves2bfloat162(l0,l1);
            *(__nv_bfloat162*)(Tl+off+4) = __halves2bfloat162(l2,l3);
        }
        __syncthreads();

        float acc[3][2][4];
        #pragma unroll
        for (int te=0;te<3;te++)
            #pragma unroll
            for (int ma=0;ma<2;ma++)
                #pragma unroll
                for (int r=0;r<4;r++) acc[te][ma][r]=0.f;

        #pragma unroll
        for (int te = 0; te < 3; ++te) {
            const unsigned aB = (te==2) ? sPl : sPh;
            const unsigned bB = (te==1) ? sTl : sTh;
            #pragma unroll
            for (int ks = 0; ks < 4; ++ks) {
                unsigned bfr[2];
                ldsm_x2(bfr, bB + swz((unsigned)((wn*8 + (la&7))*128 + ks*32 + ((la>>3)&1)*16)));
                #pragma unroll
                for (int ma = 0; ma < 2; ++ma) {
                    unsigned afr[4];
                    ldsm_x4(afr, aB + swz((unsigned)((ma*16 + la)*128 + ks*32 + ((lane>>4)&1)*16)));
                    mma16816(acc[te][ma], afr, bfr);
                }
            }
        }
        #pragma unroll
        for (int ma = 0; ma < 2; ++ma) {
            const int r0 = ma*16 + (lane>>2);
            const int c0 = wn*8 + (lane&3)*2;
            const int kgl = kt*64 + c0;
            float s00 = acc[0][ma][0]+acc[1][ma][0]+acc[2][ma][0];
            float s01 = acc[0][ma][1]+acc[1][ma][1]+acc[2][ma][1];
            float s10 = acc[0][ma][2]+acc[1][ma][2]+acc[2][ma][2];
            float s11 = acc[0][ma][3]+acc[1][ma][3]+acc[2][ma][3];
            Sc[r0*385 + kgl]       = vld[c0]   ? s00 : -3.0e38f;
            Sc[r0*385 + kgl+1]     = vld[c0+1] ? s01 : -3.0e38f;
            Sc[(r0+8)*385 + kgl]   = vld[c0]   ? s10 : -3.0e38f;
            Sc[(r0+8)*385 + kgl+1] = vld[c0+1] ? s11 : -3.0e38f;
        }
    }
    __syncthreads();

    // ---- softmax over 384 keys (8 lanes per query row) ----
    {
        const int qg = t >> 3;
        const int kb = t & 7;
        float m = -3.0e38f;
        for (int k=kb; k<NKEY; k+=8) m = fmaxf(m, Sc[qg*385+k]);
        #pragma unroll
        for (int o=4;o>0;o>>=1) m = fmaxf(m, __shfl_xor_sync(0xffffffffu, m, o));
        float ssum = 0.f;
        for (int k=kb; k<NKEY; k+=8) {
            float e = __expf(Sc[qg*385+k] - m);
            Sc[qg*385+k] = e;
            ssum += e;
        }
        #pragma unroll
        for (int o=4;o>0;o>>=1) ssum += __shfl_xor_sync(0xffffffffu, ssum, o);
        float inv = (mask[b*SSEQ+q0+qg] != 0) ? (1.f/ssum) : 0.f;
        for (int k=kb; k<NKEY; k+=8) Sc[qg*385+k] *= inv;
    }

    // ---- PV: accumulate over 6 tiles ----
    float accP[3][2][4];
    #pragma unroll
    for (int te=0;te<3;te++)
        #pragma unroll
        for (int ma=0;ma<2;ma++)
            #pragma unroll
            for (int r=0;r<4;r++) accP[te][ma][r]=0.f;

    for (int kt = 0; kt < 6; ++kt) {
        __syncthreads();
        // V tile [key][d] -> bf16 hi/lo swizzled
        #pragma unroll
        for (int u = 0; u < 4; ++u) {
            int idx = u*256 + t;
            int kk = idx >> 4, c = idx & 15;
            float4 v = make_float4(0.f,0.f,0.f,0.f);
            if (kt < 2) {
                v = *(const float4*)&g_Vc[(size_t)(b*LM + kt*64 + kk)*HD + h*DHEAD + c*4];
            } else {
                int p = g*WWIN - EXTW + (kt-2)*64 + kk;
                if (p >= 0 && p < SSEQ)
                    v = *(const float4*)&g_V[(size_t)(b*SSEQ+p)*HD + h*DHEAD + c*4];
            }
            __nv_bfloat16 h0,h1,h2,h3,l0,l1,l2,l3;
            bsplit(v.x,h0,l0); bsplit(v.y,h1,l1); bsplit(v.z,h2,l2); bsplit(v.w,h3,l3);
            unsigned off = swz((unsigned)(kk*128 + c*8));
            *(__nv_bfloat162*)(Th+off)   = __halves2bfloat162(h0,h1);
            *(__nv_bfloat162*)(Th+off+4) = __halves2bfloat162(h2,h3);
            *(__nv_bfloat162*)(Tl+off)   = __halves2bfloat162(l0,l1);
            *(__nv_bfloat162*)(Tl+off+4) = __halves2bfloat162(l2,l3);
        }
        // P slice [32][64] -> bf16 hi/lo swizzled (reuse Q buffers)
        #pragma unroll
        for (int u = 0; u < 2; ++u) {
            int el = (u*256 + t)*4;     // 2048 floats
            int q = el >> 6, k = el & 63;
            float p0 = Sc[q*385 + kt*64 + k];
            float p1 = Sc[q*385 + kt*64 + k+1];
            float p2 = Sc[q*385 + kt*64 + k+2];
            float p3 = Sc[q*385 + kt*64 + k+3];
            __nv_bfloat16 h0,h1,h2,h3,l0,l1,l2,l3;
            bsplit(p0,h0,l0); bsplit(p1,h1,l1); bsplit(p2,h2,l2); bsplit(p3,h3,l3);
            unsigned off = swz((unsigned)(q*128 + k*2));
            *(__nv_bfloat162*)(Ph+off)   = __halves2bfloat162(h0,h1);
            *(__nv_bfloat162*)(Ph+off+4) = __halves2bfloat162(h2,h3);
            *(__nv_bfloat162*)(Pl+off)   = __halves2bfloat162(l0,l1);
            *(__nv_bfloat162*)(Pl+off+4) = __halves2bfloat162(l2,l3);
        }
        __syncthreads();

        #pragma unroll
        for (int te = 0; te < 3; ++te) {
            const unsigned aB = (te==2) ? sPl : sPh;
            const unsigned bB = (te==1) ? sTl : sTh;
            #pragma unroll
            for (int ks = 0; ks < 4; ++ks) {
                unsigned bfr[2];
                // V stored [key][d] row-major => trans load for col-major B fragment
                ldsm_x2t(bfr, bB + swz((unsigned)((ks*16 + (la&7) + ((la>>3)&1)*8)*128 + wn*16)));
                #pragma unroll
                for (int ma = 0; ma < 2; ++ma) {
                    unsigned afr[4];
                    ldsm_x4(afr, aB + swz((unsigned)((ma*16 + la)*128 + ks*32 + ((lane>>4)&1)*16)));
                    mma16816(accP[te][ma], afr, bfr);
                }
            }
        }
    }

    // ---- epilogue: C bf16 hi/lo ----
    #pragma unroll
    for (int ma = 0; ma < 2; ++ma) {
        const int r0 = ma*16 + (lane>>2);
        const int d0 = wn*8 + (lane&3)*2;
        float x00 = accP[0][ma][0]+accP[1][ma][0]+accP[2][ma][0];
        float x01 = accP[0][ma][1]+accP[1][ma][1]+accP[2][ma][1];
        float x10 = accP[0][ma][2]+accP[1][ma][2]+accP[2][ma][2];
        float x11 = accP[0][ma][3]+accP[1][ma][3]+accP[2][ma][3];
        __nv_bfloat16 h0,h1,l0,l1;
        size_t off0 = (size_t)(b*SSEQ + q0 + r0)*HD + h*DHEAD + d0;
        bsplit(x00,h0,l0); bsplit(x01,h1,l1);
        *(__nv_bfloat162*)(Chi + off0) = __halves2bfloat162(h0,h1);
        *(__nv_bfloat162*)(Clo + off0) = __halves2bfloat162(l0,l1);
        size_t off1 = (size_t)(b*SSEQ + q0 + r0 + 8)*HD + h*DHEAD + d0;
        bsplit(x10,h0,l0); bsplit(x11,h1,l1);
        *(__nv_bfloat162*)(Chi + off1) = __halves2bfloat162(h0,h1);
        *(__nv_bfloat162*)(Clo + off1) = __halves2bfloat162(l0,l1);
    }
}

// ---------------- host launcher (single stream) ----------------
extern "C" void kernel_launch(void* const* d_in, const int* in_sizes, int n_in,
                              void* d_out, int out_size)
{
    const float* X    = (const float*)d_in[0];
    const int*   mask = (const int*)  d_in[1];
    const float* Wq   = (const float*)d_in[2];
    const float* bq   = (const float*)d_in[3];
    const float* Wk   = (const float*)d_in[4];
    const float* bk   = (const float*)d_in[5];
    const float* Wv   = (const float*)d_in[6];
    const float* bv   = (const float*)d_in[7];
    const float* Wo   = (const float*)d_in[8];
    const float* bo   = (const float*)d_in[9];
    const float* lnlg = (const float*)d_in[10];
    const float* lnlb = (const float*)d_in[11];
    const float* lnsg = (const float*)d_in[12];
    const float* lnsb = (const float*)d_in[13];
    const float* Wd   = (const float*)d_in[14];
    const float* bd   = (const float*)d_in[15];
    float* out = (float*)d_out;

    float *pQ,*pK,*pV,*pDl,*pKc,*pVc;
    cudaGetSymbolAddress((void**)&pQ,  g_Q);
    cudaGetSymbolAddress((void**)&pK,  g_K);
    cudaGetSymbolAddress((void**)&pV,  g_V);
    cudaGetSymbolAddress((void**)&pDl, g_Dl);
    cudaGetSymbolAddress((void**)&pKc, g_Kc);
    cudaGetSymbolAddress((void**)&pVc, g_Vc);
    __nv_bfloat16* bf;
    cudaGetSymbolAddress((void**)&bf, g_bf);

    static int init_done = 0;
    if (!init_done) {
        cudaFuncSetAttribute(attn_kernel, cudaFuncAttributeMaxDynamicSharedMemorySize, 73856);
        cudaFuncSetAttribute(gemm_mma_kernel, cudaFuncAttributeMaxDynamicSharedMemorySize, 65536);
        cudaFuncSetAttribute(proj4_kernel, cudaFuncAttributeMaxDynamicSharedMemorySize, 65536);
        init_done = 1;
    }

    const int M = BB*SSEQ;                       // 8192

    // bf16 splits + all weight transposes
    split_kernel<<<2048,256>>>(X, bf+XHI, bf+XLO, M*HD);
    transpose_split_all_kernel<<<1536,dim3(32,8)>>>(Wq, Wk, Wv, Wd, Wo, bf);

    // fused 4-projection GEMM (Q carries the 1/sqrt(DH) scale)
    proj4_kernel<<<dim3(20,64),256,65536>>>(
        bf+XHI, bf+XLO,
        bf+WQTH, bf+WQTL, bf+WKTH, bf+WKTL, bf+WVTH, bf+WVTL, bf+WDTH, bf+WDTL,
        bq, bk, bv, bd, pQ, pK, pV, pDl);

    // ln_l on K and V in one launch
    ln512x2_kernel<<<2*M,128>>>(pK, pV, M, lnlg, lnlb);

    // hs = softmax over sequence axis
    softmax_seq_kernel<<<dim3(HL/32, BB), dim3(32,32)>>>();

    // landmark Kc/Vc
    zero_kv_kernel<<<512,256>>>();
    landmark_kv_kernel<<<dim3(BB*NH, 8),256>>>();
    ln512x2_kernel<<<2*BB*LM,128>>>(pKc, pVc, BB*LM, lnsg, lnsb);

    // fused long-short attention on HMMA (writes bf16 hi/lo C directly)
    attn_kernel<<<dim3(SSEQ/QT, NH, BB), 256, 73856>>>(mask, bf+CHI, bf+CLO);

    // output projection on HMMA
    gemm_mma_kernel<<<dim3(4,64),256,65536>>>(bf+CHI, bf+CLO, bf+WOTH, bf+WOTL, bo, out, 512, 1.f);
}

// round 15
// speedup vs baseline: 1.4836x; 1.4836x over previous
#include <cuda_runtime.h>
#include <cuda_bf16.h>
#include <math.h>

#define BB 2
#define SSEQ 4096
#define NH 8
#define DHEAD 64
#define HD 512
#define LM 128
#define WWIN 128
#define EXTW 64
#define HL 1024
#define NKEY 384
#define QT 32

// ---------------- scratch (device globals; no allocations) ----------------
__device__ float g_Q [BB*SSEQ*HD];
__device__ float g_K [BB*SSEQ*HD];
__device__ float g_V [BB*SSEQ*HD];
__device__ float g_Dl[BB*SSEQ*HL];   // D logits, softmaxed in-place -> hs
__device__ float g_Kc[BB*LM*HD];
__device__ float g_Vc[BB*LM*HD];

// bf16 arena: X hi/lo, C hi/lo, transposed-weight hi/lo
#define XHI  0
#define XLO  4194304
#define CHI  8388608
#define CLO  12582912
#define WQTH 16777216
#define WQTL 17039360
#define WKTH 17301504
#define WKTL 17563648
#define WVTH 17825792
#define WVTL 18087936
#define WDTH 18350080
#define WDTL 18874368
#define WOTH 19398656
#define WOTL 19660800
__device__ __nv_bfloat16 g_bf[19922944];

// ================= helpers =================
__device__ __forceinline__ unsigned smem_u32(const void* p) {
    unsigned a;
    asm("{ .reg .u64 t; cvta.to.shared.u64 t, %1; cvt.u32.u64 %0, t; }" : "=r"(a) : "l"(p));
    return a;
}
__device__ __forceinline__ unsigned swz(unsigned b) { return b ^ ((b >> 3) & 0x70u); }

__device__ __forceinline__ void ldsm_x4(unsigned* r, unsigned addr) {
    asm volatile("ldmatrix.sync.aligned.m8n8.x4.shared.b16 {%0,%1,%2,%3}, [%4];"
        : "=r"(r[0]),"=r"(r[1]),"=r"(r[2]),"=r"(r[3]) : "r"(addr));
}
__device__ __forceinline__ void ldsm_x2(unsigned* r, unsigned addr) {
    asm volatile("ldmatrix.sync.aligned.m8n8.x2.shared.b16 {%0,%1}, [%2];"
        : "=r"(r[0]),"=r"(r[1]) : "r"(addr));
}
__device__ __forceinline__ void ldsm_x2t(unsigned* r, unsigned addr) {
    asm volatile("ldmatrix.sync.aligned.m8n8.x2.trans.shared.b16 {%0,%1}, [%2];"
        : "=r"(r[0]),"=r"(r[1]) : "r"(addr));
}
__device__ __forceinline__ void mma16816(float* c, const unsigned* a, const unsigned* b) {
    asm volatile("mma.sync.aligned.m16n8k16.row.col.f32.bf16.bf16.f32 "
        "{%0,%1,%2,%3}, {%4,%5,%6,%7}, {%8,%9}, {%0,%1,%2,%3};"
        : "+f"(c[0]),"+f"(c[1]),"+f"(c[2]),"+f"(c[3])
        : "r"(a[0]),"r"(a[1]),"r"(a[2]),"r"(a[3]), "r"(b[0]),"r"(b[1]));
}
// split one float into hi/lo bf16
__device__ __forceinline__ void bsplit(float x, __nv_bfloat16& h, __nv_bfloat16& l) {
    h = __float2bfloat16(x);
    l = __float2bfloat16(x - __bfloat162float(h));
}

// ================= bf16-split conversion kernels =================
__global__ __launch_bounds__(256) void split_kernel(
    const float* __restrict__ src, __nv_bfloat16* __restrict__ hi,
    __nv_bfloat16* __restrict__ lo, int n)
{
    int i = (blockIdx.x * 256 + threadIdx.x) * 8;
    if (i >= n) return;
    #pragma unroll
    for (int j = 0; j < 8; j += 4) {
        float4 v = *(const float4*)(src + i + j);
        __nv_bfloat16 h0,h1,h2,h3,l0,l1,l2,l3;
        bsplit(v.x,h0,l0); bsplit(v.y,h1,l1); bsplit(v.z,h2,l2); bsplit(v.w,h3,l3);
        *(__nv_bfloat162*)(hi + i + j)     = __halves2bfloat162(h0, h1);
        *(__nv_bfloat162*)(hi + i + j + 2) = __halves2bfloat162(h2, h3);
        *(__nv_bfloat162*)(lo + i + j)     = __halves2bfloat162(l0, l1);
        *(__nv_bfloat162*)(lo + i + j + 2) = __halves2bfloat162(l2, l3);
    }
}

// All 5 weights transposed+split in one launch.
__global__ __launch_bounds__(256) void transpose_split_all_kernel(
    const float* __restrict__ Wq, const float* __restrict__ Wk,
    const float* __restrict__ Wv, const float* __restrict__ Wd,
    const float* __restrict__ Wo, __nv_bfloat16* __restrict__ base)
{
    __shared__ float tile[32][33];
    const int id = blockIdx.x;
    const float* W; __nv_bfloat16 *Th, *Tl; int N, tl;
    if (id < 256)       { W = Wq; Th = base+WQTH; Tl = base+WQTL; N = 512;  tl = id; }
    else if (id < 512)  { W = Wk; Th = base+WKTH; Tl = base+WKTL; N = 512;  tl = id-256; }
    else if (id < 768)  { W = Wv; Th = base+WVTH; Tl = base+WVTL; N = 512;  tl = id-512; }
    else if (id < 1280) { W = Wd; Th = base+WDTH; Tl = base+WDTL; N = 1024; tl = id-768; }
    else                { W = Wo; Th = base+WOTH; Tl = base+WOTL; N = 512;  tl = id-1280; }
    const int nt = N >> 5;
    const int n0 = (tl % nt) * 32, k0 = (tl / nt) * 32;
    const int tx = threadIdx.x, ty = threadIdx.y;
    #pragma unroll
    for (int i = 0; i < 32; i += 8)
        tile[ty + i][tx] = W[(size_t)(k0 + ty + i) * N + n0 + tx];
    __syncthreads();
    #pragma unroll
    for (int i = 0; i < 32; i += 8) {
        float x = tile[tx][ty + i];
        __nv_bfloat16 h, l; bsplit(x, h, l);
        size_t o = (size_t)(n0 + ty + i) * 512 + k0 + tx;
        Th[o] = h; Tl[o] = l;
    }
}

// ================= bf16-split GEMM core (mma.sync HMMA) =================
#define GEMM_CORE(Ahi, Alo, Bhi, Blo, Cptr, Nw, alphav, biasptr)                      \
{                                                                                      \
    float acc[4][4][4];                                                                \
    _Pragma("unroll")                                                                  \
    for (int i=0;i<4;i++) _Pragma("unroll") for (int j=0;j<4;j++)                      \
        _Pragma("unroll") for (int k=0;k<4;k++) acc[i][j][k]=0.f;                      \
    {                                                                                  \
        uint4 rg[8];                                                                   \
        _Pragma("unroll")                                                              \
        for (int i = 0; i < 4; ++i) {                                                  \
            int e = i*256 + tid; int r = e >> 3, u = e & 7;                            \
            rg[i]   = *(const uint4*)((Ahi) + (size_t)(bm*128 + r)*512 + u*8);         \
            rg[4+i] = *(const uint4*)((Bhi) + (size_t)(lbn*128 + r)*512 + u*8);        \
        }                                                                              \
        _Pragma("unroll")                                                              \
        for (int i = 0; i < 4; ++i) {                                                  \
            int e = i*256 + tid; int r = e >> 3, u = e & 7;                            \
            unsigned off = swz((unsigned)(r*128 + u*16));                              \
            *(uint4*)(smem + off)          = rg[i];                                    \
            *(uint4*)(smem + 16384u + off) = rg[4+i];                                  \
        }                                                                              \
    }                                                                                  \
    __syncthreads();                                                                   \
    for (int c = 0; c < 24; ++c) {                                                     \
        uint4 rn[8];                                                                   \
        if (c < 23) {                                                                  \
            const int cn = c + 1;                                                      \
            const __nv_bfloat16* As = (cn >= 16) ? (Alo) : (Ahi);                      \
            const __nv_bfloat16* Bs = (cn >= 8 && cn < 16) ? (Blo) : (Bhi);            \
            const int kc = cn & 7;                                                     \
            _Pragma("unroll")                                                          \
            for (int i = 0; i < 4; ++i) {                                              \
                int e = i*256 + tid; int r = e >> 3, u = e & 7;                        \
                rn[i]   = *(const uint4*)(As + (size_t)(bm*128 + r)*512 + kc*64 + u*8);\
                rn[4+i] = *(const uint4*)(Bs + (size_t)(lbn*128 + r)*512 + kc*64 + u*8);\
            }                                                                          \
        }                                                                              \
        gemm_compute_stage(sb, c & 1, wm, wn, lane, acc);                              \
        if (c < 23) {                                                                  \
            const unsigned basest = (unsigned)((c + 1) & 1) * 32768u;                  \
            _Pragma("unroll")                                                          \
            for (int i = 0; i < 4; ++i) {                                              \
                int e = i*256 + tid; int r = e >> 3, u = e & 7;                        \
                unsigned off = swz((unsigned)(r*128 + u*16));                          \
                *(uint4*)(smem + basest + off)          = rn[i];                       \
                *(uint4*)(smem + basest + 16384u + off) = rn[4+i];                     \
            }                                                                          \
        }                                                                              \
        __syncthreads();                                                               \
    }                                                                                  \
    _Pragma("unroll")                                                                  \
    for (int ma = 0; ma < 4; ++ma) {                                                   \
        const int row = bm*128 + wm*64 + ma*16 + (lane >> 2);                          \
        _Pragma("unroll")                                                              \
        for (int na = 0; na < 4; ++na) {                                               \
            const int col = lbn*128 + wn*32 + na*8 + (lane & 3)*2;                     \
            const float b0 = (biasptr)[col], b1 = (biasptr)[col+1];                    \
            float2 o0, o1;                                                             \
            o0.x = (alphav)*(acc[ma][na][0] + b0);                                     \
            o0.y = (alphav)*(acc[ma][na][1] + b1);                                     \
            o1.x = (alphav)*(acc[ma][na][2] + b0);                                     \
            o1.y = (alphav)*(acc[ma][na][3] + b1);                                     \
            *(float2*)((Cptr) + (size_t)row*(Nw) + col)     = o0;                      \
            *(float2*)((Cptr) + (size_t)(row+8)*(Nw) + col) = o1;                      \
        }                                                                              \
    }                                                                                  \
}

__device__ __forceinline__ void gemm_compute_stage(
    unsigned sb, int st, int wm, int wn, int lane, float acc[4][4][4])
{
    const unsigned sA = sb + (unsigned)st * 32768u;
    const unsigned sB = sA + 16384u;
    const int la = lane & 15;
    #pragma unroll
    for (int ks = 0; ks < 4; ++ks) {
        unsigned a[4][4], b[4][2];
        #pragma unroll
        for (int ma = 0; ma < 4; ++ma) {
            unsigned arow = (unsigned)(wm*64 + ma*16 + la);
            unsigned ab   = (unsigned)(ks*32 + ((lane>>4)&1)*16);
            ldsm_x4(a[ma], sA + swz(arow*128u + ab));
        }
        #pragma unroll
        for (int na = 0; na < 4; ++na) {
            unsigned brow = (unsigned)(wn*32 + na*8 + (la & 7));
            unsigned bb   = (unsigned)(ks*32 + ((la>>3)&1)*16);
            ldsm_x2(b[na], sB + swz(brow*128u + bb));
        }
        #pragma unroll
        for (int ma = 0; ma < 4; ++ma)
            #pragma unroll
            for (int na = 0; na < 4; ++na)
                mma16816(acc[ma][na], a[ma], b[na]);
    }
}

// generic single GEMM (used for the Wo projection)
__global__ __launch_bounds__(256) void gemm_mma_kernel(
    const __nv_bfloat16* __restrict__ Ahi, const __nv_bfloat16* __restrict__ Alo,
    const __nv_bfloat16* __restrict__ Bhi, const __nv_bfloat16* __restrict__ Blo,
    const float* __restrict__ bias, float* __restrict__ C, int N, float alpha)
{
    extern __shared__ __align__(128) char smem[];
    const unsigned sb = smem_u32(smem);
    const int tid  = threadIdx.x;
    const int lane = tid & 31, wid = tid >> 5;
    const int wm = wid >> 2, wn = wid & 3;
    const int bm = blockIdx.y, lbn = blockIdx.x;
    GEMM_CORE(Ahi, Alo, Bhi, Blo, C, N, alpha, bias);
}

// fused 4-projection GEMM: bn 0-3 Q, 4-7 K, 8-11 V, 12-19 D-logits
__global__ __launch_bounds__(256) void proj4_kernel(
    const __nv_bfloat16* __restrict__ Ahi, const __nv_bfloat16* __restrict__ Alo,
    const __nv_bfloat16* __restrict__ Qh, const __nv_bfloat16* __restrict__ Ql,
    const __nv_bfloat16* __restrict__ Kh, const __nv_bfloat16* __restrict__ Kl,
    const __nv_bfloat16* __restrict__ Vh, const __nv_bfloat16* __restrict__ Vl,
    const __nv_bfloat16* __restrict__ Dh, const __nv_bfloat16* __restrict__ Dlw,
    const float* __restrict__ bq, const float* __restrict__ bk,
    const float* __restrict__ bv, const float* __restrict__ bd,
    float* __restrict__ oQ, float* __restrict__ oK,
    float* __restrict__ oV, float* __restrict__ oD)
{
    extern __shared__ __align__(128) char smem[];
    const unsigned sb = smem_u32(smem);
    const int tid  = threadIdx.x;
    const int lane = tid & 31, wid = tid >> 5;
    const int wm = wid >> 2, wn = wid & 3;
    const int bm = blockIdx.y;
    const int bn = blockIdx.x;

    const __nv_bfloat16 *Bh, *Bl; const float* bias; float* Cp;
    int lbn, N; float alpha = 1.f;
    if (bn < 4)       { lbn = bn;    Bh = Qh; Bl = Ql;  bias = bq; Cp = oQ; N = 512; alpha = 0.125f; }
    else if (bn < 8)  { lbn = bn-4;  Bh = Kh; Bl = Kl;  bias = bk; Cp = oK; N = 512; }
    else if (bn < 12) { lbn = bn-8;  Bh = Vh; Bl = Vl;  bias = bv; Cp = oV; N = 512; }
    else              { lbn = bn-12; Bh = Dh; Bl = Dlw; bias = bd; Cp = oD; N = 1024; }
    GEMM_CORE(Ahi, Alo, Bh, Bl, Cp, N, alpha, bias);
}

// ---------------- LayerNorm over rows of 512, two tensors in one launch ----------------
__global__ __launch_bounds__(128) void ln512x2_kernel(
    float* __restrict__ Y1, float* __restrict__ Y2, int M1,
    const float* __restrict__ gam, const float* __restrict__ bet)
{
    const int row = blockIdx.x;
    float* x = (row < M1) ? (Y1 + (size_t)row * HD) : (Y2 + (size_t)(row - M1) * HD);
    const int t = threadIdx.x;
    float4 v = *(float4*)(x + t*4);
    float s  = v.x+v.y+v.z+v.w;
    float ss = v.x*v.x + v.y*v.y + v.z*v.z + v.w*v.w;
    #pragma unroll
    for (int o=16;o>0;o>>=1) {
        s  += __shfl_xor_sync(0xffffffffu, s, o);
        ss += __shfl_xor_sync(0xffffffffu, ss, o);
    }
    __shared__ float rs[4], rss[4];
    if ((t&31)==0) { rs[t>>5]=s; rss[t>>5]=ss; }
    __syncthreads();
    s  = rs[0]+rs[1]+rs[2]+rs[3];
    ss = rss[0]+rss[1]+rss[2]+rss[3];
    const float mean = s * (1.f/HD);
    const float var  = ss*(1.f/HD) - mean*mean;
    const float inv  = rsqrtf(var + 1e-5f);
    float4 g4 = *(const float4*)(gam + t*4);
    float4 b4 = *(const float4*)(bet + t*4);
    v.x = (v.x-mean)*inv*g4.x + b4.x;
    v.y = (v.y-mean)*inv*g4.y + b4.y;
    v.z = (v.z-mean)*inv*g4.z + b4.z;
    v.w = (v.w-mean)*inv*g4.w + b4.w;
    *(float4*)(x + t*4) = v;
}

// ---------------- softmax over sequence axis of g_Dl (B,S,HL), in-place ----------------
__global__ void softmax_seq_kernel()
{
    const int b = blockIdx.y;
    const int j = blockIdx.x*32 + threadIdx.x;
    const int ty = threadIdx.y;
    float m = -3.0e38f;
    for (int s = ty; s < SSEQ; s += 32)
        m = fmaxf(m, g_Dl[(size_t)(b*SSEQ+s)*HL + j]);
    __shared__ float sM[32][33];
    __shared__ float sS[32][33];
    sM[ty][threadIdx.x] = m;
    __syncthreads();
    float M = -3.0e38f;
    #pragma unroll
    for (int i=0;i<32;i++) M = fmaxf(M, sM[i][threadIdx.x]);
    float ssum = 0.f;
    for (int s = ty; s < SSEQ; s += 32)
        ssum += __expf(g_Dl[(size_t)(b*SSEQ+s)*HL + j] - M);
    sS[ty][threadIdx.x] = ssum;
    __syncthreads();
    float tot = 0.f;
    #pragma unroll
    for (int i=0;i<32;i++) tot += sS[i][threadIdx.x];
    const float inv = 1.f / tot;
    for (int s = ty; s < SSEQ; s += 32) {
        size_t off = (size_t)(b*SSEQ+s)*HL + j;
        g_Dl[off] = __expf(g_Dl[off] - M) * inv;
    }
}

// ---------------- zero Kc/Vc ----------------
__global__ void zero_kv_kernel()
{
    int i = blockIdx.x*256 + threadIdx.x;
    if (i < BB*LM*HD) { g_Kc[i]=0.f; g_Vc[i]=0.f; }
}

// ---------------- Kc = hs^T @ K, Vc = hs^T @ V (per b,h), split-K=8 with atomics ----------------
__global__ __launch_bounds__(256) void landmark_kv_kernel()
{
    const int b = blockIdx.x >> 3;
    const int h = blockIdx.x & 7;
    const int s0 = blockIdx.y * (SSEQ/8);
    __shared__ float sh[8][128];
    __shared__ float sk[8][64];
    __shared__ float sv[8][64];
    const int t = threadIdx.x;
    const int d  = t & 63;
    const int lg = t >> 6;
    float aK[32], aV[32];
    #pragma unroll
    for (int i=0;i<32;i++){aK[i]=0.f;aV[i]=0.f;}

    for (int sc = 0; sc < SSEQ/8; sc += 8) {
        #pragma unroll
        for (int u = 0; u < 8; ++u) {
            int idx = u*256 + t;
            int si = idx >> 8;
            int c  = idx & 255;
            int s  = s0 + sc + si;
            if (c < 128)      sh[si][c]     = g_Dl[(size_t)(b*SSEQ+s)*HL + h*LM + c];
            else if (c < 192) sk[si][c-128] = g_K [(size_t)(b*SSEQ+s)*HD + h*DHEAD + (c-128)];
            else              sv[si][c-192] = g_V [(size_t)(b*SSEQ+s)*HD + h*DHEAD + (c-192)];
        }
        __syncthreads();
        #pragma unroll
        for (int si=0; si<8; ++si) {
            const float kv = sk[si][d];
            const float vv = sv[si][d];
            const float4* hp = (const float4*)&sh[si][lg*32];
            #pragma unroll
            for (int i4=0;i4<8;i4++){
                float4 h4 = hp[i4];
                aK[i4*4+0] += h4.x*kv; aV[i4*4+0] += h4.x*vv;
                aK[i4*4+1] += h4.y*kv; aV[i4*4+1] += h4.y*vv;
                aK[i4*4+2] += h4.z*kv; aV[i4*4+2] += h4.z*vv;
                aK[i4*4+3] += h4.w*kv; aV[i4*4+3] += h4.w*vv;
            }
        }
        __syncthreads();
    }
    #pragma unroll
    for (int i=0;i<32;i++){
        const int l = lg*32 + i;
        atomicAdd(&g_Kc[(size_t)(b*LM+l)*HD + h*DHEAD + d], aK[i]);
        atomicAdd(&g_Vc[(size_t)(b*LM+l)*HD + h*DHEAD + d], aV[i]);
    }
}

// ---------------- fused attention on HMMA: QK^T + softmax + PV, bf16-split 3-term ----------------
// smem: Sc 32x385 f32 (49280 B) | Ph 4KB | Pl 4KB (Q hi/lo, reused for P) | Th 8KB | Tl 8KB
__global__ __launch_bounds__(256) void attn_kernel(
    const int* __restrict__ mask,
    __nv_bfloat16* __restrict__ Chi, __nv_bfloat16* __restrict__ Clo)
{
    extern __shared__ __align__(128) char smem[];
    float* Sc = (float*)smem;
    char* Ph = smem + 49280;
    char* Pl = Ph + 4096;
    char* Th = Pl + 4096;
    char* Tl = Th + 8192;
    __shared__ int vld[64];

    const unsigned sb  = smem_u32(smem);
    const unsigned sPh = sb + 49280u, sPl = sPh + 4096u;
    const unsigned sTh = sPl + 4096u, sTl = sTh + 8192u;

    const int b  = blockIdx.z;
    const int h  = blockIdx.y;
    const int q0 = blockIdx.x * QT;
    const int g  = q0 >> 7;
    const int t  = threadIdx.x;
    const int lane = t & 31, wn = t >> 5;
    const int la = lane & 15;

    // ---- Q (32x64 fp32) -> bf16 hi/lo swizzled smem ----
    #pragma unroll
    for (int u = 0; u < 2; ++u) {
        int idx = u*256 + t;            // 512 float4
        int q = idx >> 4, c = idx & 15;
        float4 v = *(const float4*)&g_Q[(size_t)(b*SSEQ+q0+q)*HD + h*DHEAD + c*4];
        __nv_bfloat16 h0,h1,h2,h3,l0,l1,l2,l3;
        bsplit(v.x,h0,l0); bsplit(v.y,h1,l1); bsplit(v.z,h2,l2); bsplit(v.w,h3,l3);
        unsigned off = swz((unsigned)(q*128 + c*8));
        *(__nv_bfloat162*)(Ph+off)   = __halves2bfloat162(h0,h1);
        *(__nv_bfloat162*)(Ph+off+4) = __halves2bfloat162(h2,h3);
        *(__nv_bfloat162*)(Pl+off)   = __halves2bfloat162(l0,l1);
        *(__nv_bfloat162*)(Pl+off+4) = __halves2bfloat162(l2,l3);
    }

    // ---- score tiles ----
    for (int kt = 0; kt < 6; ++kt) {
        __syncthreads();
        if (t < 64) {
            int ok = 1;
            if (kt >= 2) {
                int p = g*WWIN - EXTW + (kt-2)*64 + t;
                ok = (p >= 0 && p < SSEQ) ? (mask[b*SSEQ+p] != 0) : 0;
            }
            vld[t] = ok;
        }
        #pragma unroll
        for (int u = 0; u < 4; ++u) {
            int idx = u*256 + t;        // 1024 float4
            int kk = idx >> 4, c = idx & 15;
            float4 v = make_float4(0.f,0.f,0.f,0.f);
            if (kt < 2) {
                v = *(const float4*)&g_Kc[(size_t)(b*LM + kt*64 + kk)*HD + h*DHEAD + c*4];
            } else {
                int p = g*WWIN - EXTW + (kt-2)*64 + kk;
                if (p >= 0 && p < SSEQ)
                    v = *(const float4*)&g_K[(size_t)(b*SSEQ+p)*HD + h*DHEAD + c*4];
            }
            __nv_bfloat16 h0,h1,h2,h3,l0,l1,l2,l3;
            bsplit(v.x,h0,l0); bsplit(v.y,h1,l1); bsplit(v.z,h2,l2); bsplit(v.w,h3,l3);
            unsigned off = swz((unsigned)(kk*128 + c*8));
            *(__nv_bfloat162*)(Th+off)   = __halves2bfloat162(h0,h1);
            *(__nv_bfloat162*)(Th+off+4) = __halves2bfloat162(h2,h3);
            *(__nv_bfloat162*)(Tl+off)   = __halves2bfloat162(l0,l1);
            *(__nv_bfloat162*)(Tl+off+4) = __halves2bfloat162(l2,l3);
        }
        __syncthreads();

        float acc[3][2][4];
        #pragma unroll
        for (int te=0;te<3;te++)
            #pragma unroll
            for (int ma=0;ma<2;ma++)
                #pragma unroll
                for (int r=0;r<4;r++) acc[te][ma][r]=0.f;

        #pragma unroll
        for (int te = 0; te < 3; ++te) {
            const unsigned aB = (te==2) ? sPl : sPh;
            const unsigned bB = (te==1) ? sTl : sTh;
            #pragma unroll
            for (int ks = 0; ks < 4; ++ks) {
                unsigned bfr[2];
                ldsm_x2(bfr, bB + swz((unsigned)((wn*8 + (la&7))*128 + ks*32 + ((la>>3)&1)*16)));
                #pragma unroll
                for (int ma = 0; ma < 2; ++ma) {
                    unsigned afr[4];
                    ldsm_x4(afr, aB + swz((unsigned)((ma*16 + la)*128 + ks*32 + ((lane>>4)&1)*16)));
                    mma16816(acc[te][ma], afr, bfr);
                }
            }
        }
        #pragma unroll
        for (int ma = 0; ma < 2; ++ma) {
            const int r0 = ma*16 + (lane>>2);
            const int c0 = wn*8 + (lane&3)*2;
            const int kgl = kt*64 + c0;
            float s00 = acc[0][ma][0]+acc[1][ma][0]+acc[2][ma][0];
            float s01 = acc[0][ma][1]+acc[1][ma][1]+acc[2][ma][1];
            float s10 = acc[0][ma][2]+acc[1][ma][2]+acc[2][ma][2];
            float s11 = acc[0][ma][3]+acc[1][ma][3]+acc[2][ma][3];
            Sc[r0*385 + kgl]       = vld[c0]   ? s00 : -3.0e38f;
            Sc[r0*385 + kgl+1]     = vld[c0+1] ? s01 : -3.0e38f;
            Sc[(r0+8)*385 + kgl]   = vld[c0]   ? s10 : -3.0e38f;
            Sc[(r0+8)*385 + kgl+1] = vld[c0+1] ? s11 : -3.0e38f;
        }
    }
    __syncthreads();

    // ---- softmax over 384 keys (8 lanes per query row) ----
    {
        const int qg = t >> 3;
        const int kb = t & 7;
        float m = -3.0e38f;
        for (int k=kb; k<NKEY; k+=8) m = fmaxf(m, Sc[qg*385+k]);
        #pragma unroll
        for (int o=4;o>0;o>>=1) m = fmaxf(m, __shfl_xor_sync(0xffffffffu, m, o));
        float ssum = 0.f;
        for (int k=kb; k<NKEY; k+=8) {
            float e = __expf(Sc[qg*385+k] - m);
            Sc[qg*385+k] = e;
            ssum += e;
        }
        #pragma unroll
        for (int o=4;o>0;o>>=1) ssum += __shfl_xor_sync(0xffffffffu, ssum, o);
        float inv = (mask[b*SSEQ+q0+qg] != 0) ? (1.f/ssum) : 0.f;
        for (int k=kb; k<NKEY; k+=8) Sc[qg*385+k] *= inv;
    }

    // ---- PV: accumulate over 6 tiles ----
    float accP[3][2][4];
    #pragma unroll
    for (int te=0;te<3;te++)
        #pragma unroll
        for (int ma=0;ma<2;ma++)
            #pragma unroll
            for (int r=0;r<4;r++) accP[te][ma][r]=0.f;

    for (int kt = 0; kt < 6; ++kt) {
        __syncthreads();
        // V tile [key][d] -> bf16 hi/lo swizzled
        #pragma unroll
        for (int u = 0; u < 4; ++u) {
            int idx = u*256 + t;
            int kk = idx >> 4, c = idx & 15;
            float4 v = make_float4(0.f,0.f,0.f,0.f);
            if (kt < 2) {
                v = *(const float4*)&g_Vc[(size_t)(b*LM + kt*64 + kk)*HD + h*DHEAD + c*4];
            } else {
                int p = g*WWIN - EXTW + (kt-2)*64 + kk;
                if (p >= 0 && p < SSEQ)
                    v = *(const float4*)&g_V[(size_t)(b*SSEQ+p)*HD + h*DHEAD + c*4];
            }
            __nv_bfloat16 h0,h1,h2,h3,l0,l1,l2,l3;
            bsplit(v.x,h0,l0); bsplit(v.y,h1,l1); bsplit(v.z,h2,l2); bsplit(v.w,h3,l3);
            unsigned off = swz((unsigned)(kk*128 + c*8));
            *(__nv_bfloat162*)(Th+off)   = __halves2bfloat162(h0,h1);
            *(__nv_bfloat162*)(Th+off+4) = __halves2bfloat162(h2,h3);
            *(__nv_bfloat162*)(Tl+off)   = __halves2bfloat162(l0,l1);
            *(__nv_bfloat162*)(Tl+off+4) = __halves2bfloat162(l2,l3);
        }
        // P slice [32][64] -> bf16 hi/lo swizzled (reuse Q buffers)
        #pragma unroll
        for (int u = 0; u < 2; ++u) {
            int el = (u*256 + t)*4;     // 2048 floats
            int q = el >> 6, k = el & 63;
            float p0 = Sc[q*385 + kt*64 + k];
            float p1 = Sc[q*385 + kt*64 + k+1];
            float p2 = Sc[q*385 + kt*64 + k+2];
            float p3 = Sc[q*385 + kt*64 + k+3];
            __nv_bfloat16 h0,h1,h2,h3,l0,l1,l2,l3;
            bsplit(p0,h0,l0); bsplit(p1,h1,l1); bsplit(p2,h2,l2); bsplit(p3,h3,l3);
            unsigned off = swz((unsigned)(q*128 + k*2));
            *(__nv_bfloat162*)(Ph+off)   = __halves2bfloat162(h0,h1);
            *(__nv_bfloat162*)(Ph+off+4) = __halves2bfloat162(h2,h3);
            *(__nv_bfloat162*)(Pl+off)   = __halves2bfloat162(l0,l1);
            *(__nv_bfloat162*)(Pl+off+4) = __halves2bfloat162(l2,l3);
        }
        __syncthreads();

        #pragma unroll
        for (int te = 0; te < 3; ++te) {
            const unsigned aB = (te==2) ? sPl : sPh;
            const unsigned bB = (te==1) ? sTl : sTh;
            #pragma unroll
            for (int ks = 0; ks < 4; ++ks) {
                unsigned bfr[2];
                // V stored [key][d] row-major => trans load for col-major B fragment
                ldsm_x2t(bfr, bB + swz((unsigned)((ks*16 + (la&7) + ((la>>3)&1)*8)*128 + wn*16)));
                #pragma unroll
                for (int ma = 0; ma < 2; ++ma) {
                    unsigned afr[4];
                    ldsm_x4(afr, aB + swz((unsigned)((ma*16 + la)*128 + ks*32 + ((lane>>4)&1)*16)));
                    mma16816(accP[te][ma], afr, bfr);
                }
            }
        }
    }

    // ---- epilogue: C bf16 hi/lo ----
    #pragma unroll
    for (int ma = 0; ma < 2; ++ma) {
        const int r0 = ma*16 + (lane>>2);
        const int d0 = wn*8 + (lane&3)*2;
        float x00 = accP[0][ma][0]+accP[1][ma][0]+accP[2][ma][0];
        float x01 = accP[0][ma][1]+accP[1][ma][1]+accP[2][ma][1];
        float x10 = accP[0][ma][2]+accP[1][ma][2]+accP[2][ma][2];
        float x11 = accP[0][ma][3]+accP[1][ma][3]+accP[2][ma][3];
        __nv_bfloat16 h0,h1,l0,l1;
        size_t off0 = (size_t)(b*SSEQ + q0 + r0)*HD + h*DHEAD + d0;
        bsplit(x00,h0,l0); bsplit(x01,h1,l1);
        *(__nv_bfloat162*)(Chi + off0) = __halves2bfloat162(h0,h1);
        *(__nv_bfloat162*)(Clo + off0) = __halves2bfloat162(l0,l1);
        size_t off1 = (size_t)(b*SSEQ + q0 + r0 + 8)*HD + h*DHEAD + d0;
        bsplit(x10,h0,l0); bsplit(x11,h1,l1);
        *(__nv_bfloat162*)(Chi + off1) = __halves2bfloat162(h0,h1);
        *(__nv_bfloat162*)(Clo + off1) = __halves2bfloat162(l0,l1);
    }
}

// ---------------- host launcher (single stream) ----------------
extern "C" void kernel_launch(void* const* d_in, const int* in_sizes, int n_in,
                              void* d_out, int out_size)
{
    const float* X    = (const float*)d_in[0];
    const int*   mask = (const int*)  d_in[1];
    const float* Wq   = (const float*)d_in[2];
    const float* bq   = (const float*)d_in[3];
    const float* Wk   = (const float*)d_in[4];
    const float* bk   = (const float*)d_in[5];
    const float* Wv   = (const float*)d_in[6];
    const float* bv   = (const float*)d_in[7];
    const float* Wo   = (const float*)d_in[8];
    const float* bo   = (const float*)d_in[9];
    const float* lnlg = (const float*)d_in[10];
    const float* lnlb = (const float*)d_in[11];
    const float* lnsg = (const float*)d_in[12];
    const float* lnsb = (const float*)d_in[13];
    const float* Wd   = (const float*)d_in[14];
    const float* bd   = (const float*)d_in[15];
    float* out = (float*)d_out;

    float *pQ,*pK,*pV,*pDl,*pKc,*pVc;
    cudaGetSymbolAddress((void**)&pQ,  g_Q);
    cudaGetSymbolAddress((void**)&pK,  g_K);
    cudaGetSymbolAddress((void**)&pV,  g_V);
    cudaGetSymbolAddress((void**)&pDl, g_Dl);
    cudaGetSymbolAddress((void**)&pKc, g_Kc);
    cudaGetSymbolAddress((void**)&pVc, g_Vc);
    __nv_bfloat16* bf;
    cudaGetSymbolAddress((void**)&bf, g_bf);

    static int init_done = 0;
    if (!init_done) {
        cudaFuncSetAttribute(attn_kernel, cudaFuncAttributeMaxDynamicSharedMemorySize, 73856);
        cudaFuncSetAttribute(gemm_mma_kernel, cudaFuncAttributeMaxDynamicSharedMemorySize, 65536);
        cudaFuncSetAttribute(proj4_kernel, cudaFuncAttributeMaxDynamicSharedMemorySize, 65536);
        init_done = 1;
    }

    const int M = BB*SSEQ;                       // 8192

    // bf16 splits + all weight transposes
    split_kernel<<<2048,256>>>(X, bf+XHI, bf+XLO, M*HD);
    transpose_split_all_kernel<<<1536,dim3(32,8)>>>(Wq, Wk, Wv, Wd, Wo, bf);

    // fused 4-projection GEMM (Q carries the 1/sqrt(DH) scale)
    proj4_kernel<<<dim3(20,64),256,65536>>>(
        bf+XHI, bf+XLO,
        bf+WQTH, bf+WQTL, bf+WKTH, bf+WKTL, bf+WVTH, bf+WVTL, bf+WDTH, bf+WDTL,
        bq, bk, bv, bd, pQ, pK, pV, pDl);

    // ln_l on K and V in one launch
    ln512x2_kernel<<<2*M,128>>>(pK, pV, M, lnlg, lnlb);

    // hs = softmax over sequence axis
    softmax_seq_kernel<<<dim3(HL/32, BB), dim3(32,32)>>>();

    // landmark Kc/Vc
    zero_kv_kernel<<<512,256>>>();
    landmark_kv_kernel<<<dim3(BB*NH, 8),256>>>();
    ln512x2_kernel<<<2*BB*LM,128>>>(pKc, pVc, BB*LM, lnsg, lnsb);

    // fused long-short attention on HMMA (writes bf16 hi/lo C directly)
    attn_kernel<<<dim3(SSEQ/QT, NH, BB), 256, 73856>>>(mask, bf+CHI, bf+CLO);

    // output projection on HMMA
    gemm_mma_kernel<<<dim3(4,64),256,65536>>>(bf+CHI, bf+CLO, bf+WOTH, bf+WOTL, bo, out, 512, 1.f);
}

// round 16
// speedup vs baseline: 1.8813x; 1.2680x over previous
#include <cuda_runtime.h>
#include <cuda_bf16.h>
#include <math.h>

#define BB 2
#define SSEQ 4096
#define NH 8
#define DHEAD 64
#define HD 512
#define LM 128
#define WWIN 128
#define EXTW 64
#define HL 1024
#define NKEY 384
#define QT 32

// ---------------- scratch (device globals; no allocations) ----------------
__device__ float g_Q [BB*SSEQ*HD];
__device__ float g_K [BB*SSEQ*HD];
__device__ float g_V [BB*SSEQ*HD];
__device__ float g_Dl[BB*SSEQ*HL];   // D logits -> unnormalized exp (after softmax_seq)
__device__ float g_inv[BB*HL];       // per-column 1/sum for hs softmax
__device__ float g_Kc[BB*LM*HD];
__device__ float g_Vc[BB*LM*HD];

// bf16 arena: X hi/lo, C hi/lo, transposed-weight hi/lo
#define XHI  0
#define XLO  4194304
#define CHI  8388608
#define CLO  12582912
#define WQTH 16777216
#define WQTL 17039360
#define WKTH 17301504
#define WKTL 17563648
#define WVTH 17825792
#define WVTL 18087936
#define WDTH 18350080
#define WDTL 18874368
#define WOTH 19398656
#define WOTL 19660800
__device__ __nv_bfloat16 g_bf[19922944];

// ================= helpers =================
__device__ __forceinline__ unsigned smem_u32(const void* p) {
    unsigned a;
    asm("{ .reg .u64 t; cvta.to.shared.u64 t, %1; cvt.u32.u64 %0, t; }" : "=r"(a) : "l"(p));
    return a;
}
__device__ __forceinline__ unsigned swz(unsigned b) { return b ^ ((b >> 3) & 0x70u); }

__device__ __forceinline__ void ldsm_x4(unsigned* r, unsigned addr) {
    asm volatile("ldmatrix.sync.aligned.m8n8.x4.shared.b16 {%0,%1,%2,%3}, [%4];"
        : "=r"(r[0]),"=r"(r[1]),"=r"(r[2]),"=r"(r[3]) : "r"(addr));
}
__device__ __forceinline__ void ldsm_x2(unsigned* r, unsigned addr) {
    asm volatile("ldmatrix.sync.aligned.m8n8.x2.shared.b16 {%0,%1}, [%2];"
        : "=r"(r[0]),"=r"(r[1]) : "r"(addr));
}
__device__ __forceinline__ void ldsm_x2t(unsigned* r, unsigned addr) {
    asm volatile("ldmatrix.sync.aligned.m8n8.x2.trans.shared.b16 {%0,%1}, [%2];"
        : "=r"(r[0]),"=r"(r[1]) : "r"(addr));
}
__device__ __forceinline__ void mma16816(float* c, const unsigned* a, const unsigned* b) {
    asm volatile("mma.sync.aligned.m16n8k16.row.col.f32.bf16.bf16.f32 "
        "{%0,%1,%2,%3}, {%4,%5,%6,%7}, {%8,%9}, {%0,%1,%2,%3};"
        : "+f"(c[0]),"+f"(c[1]),"+f"(c[2]),"+f"(c[3])
        : "r"(a[0]),"r"(a[1]),"r"(a[2]),"r"(a[3]), "r"(b[0]),"r"(b[1]));
}
__device__ __forceinline__ void bsplit(float x, __nv_bfloat16& h, __nv_bfloat16& l) {
    h = __float2bfloat16(x);
    l = __float2bfloat16(x - __bfloat162float(h));
}

// ================= bf16-split conversion kernels =================
__global__ __launch_bounds__(256) void split_kernel(
    const float* __restrict__ src, __nv_bfloat16* __restrict__ hi,
    __nv_bfloat16* __restrict__ lo, int n)
{
    int i = (blockIdx.x * 256 + threadIdx.x) * 8;
    if (i >= n) return;
    #pragma unroll
    for (int j = 0; j < 8; j += 4) {
        float4 v = *(const float4*)(src + i + j);
        __nv_bfloat16 h0,h1,h2,h3,l0,l1,l2,l3;
        bsplit(v.x,h0,l0); bsplit(v.y,h1,l1); bsplit(v.z,h2,l2); bsplit(v.w,h3,l3);
        *(__nv_bfloat162*)(hi + i + j)     = __halves2bfloat162(h0, h1);
        *(__nv_bfloat162*)(hi + i + j + 2) = __halves2bfloat162(h2, h3);
        *(__nv_bfloat162*)(lo + i + j)     = __halves2bfloat162(l0, l1);
        *(__nv_bfloat162*)(lo + i + j + 2) = __halves2bfloat162(l2, l3);
    }
}

// All 5 weights transposed+split in one launch.
__global__ __launch_bounds__(256) void transpose_split_all_kernel(
    const float* __restrict__ Wq, const float* __restrict__ Wk,
    const float* __restrict__ Wv, const float* __restrict__ Wd,
    const float* __restrict__ Wo, __nv_bfloat16* __restrict__ base)
{
    __shared__ float tile[32][33];
    const int id = blockIdx.x;
    const float* W; __nv_bfloat16 *Th, *Tl; int N, tl;
    if (id < 256)       { W = Wq; Th = base+WQTH; Tl = base+WQTL; N = 512;  tl = id; }
    else if (id < 512)  { W = Wk; Th = base+WKTH; Tl = base+WKTL; N = 512;  tl = id-256; }
    else if (id < 768)  { W = Wv; Th = base+WVTH; Tl = base+WVTL; N = 512;  tl = id-512; }
    else if (id < 1280) { W = Wd; Th = base+WDTH; Tl = base+WDTL; N = 1024; tl = id-768; }
    else                { W = Wo; Th = base+WOTH; Tl = base+WOTL; N = 512;  tl = id-1280; }
    const int nt = N >> 5;
    const int n0 = (tl % nt) * 32, k0 = (tl / nt) * 32;
    const int tx = threadIdx.x, ty = threadIdx.y;
    #pragma unroll
    for (int i = 0; i < 32; i += 8)
        tile[ty + i][tx] = W[(size_t)(k0 + ty + i) * N + n0 + tx];
    __syncthreads();
    #pragma unroll
    for (int i = 0; i < 32; i += 8) {
        float x = tile[tx][ty + i];
        __nv_bfloat16 h, l; bsplit(x, h, l);
        size_t o = (size_t)(n0 + ty + i) * 512 + k0 + tx;
        Th[o] = h; Tl[o] = l;
    }
}

// ================= bf16-split GEMM core (mma.sync HMMA) =================
#define GEMM_CORE(Ahi, Alo, Bhi, Blo, Cptr, Nw, alphav, biasptr)                      \
{                                                                                      \
    float acc[4][4][4];                                                                \
    _Pragma("unroll")                                                                  \
    for (int i=0;i<4;i++) _Pragma("unroll") for (int j=0;j<4;j++)                      \
        _Pragma("unroll") for (int k=0;k<4;k++) acc[i][j][k]=0.f;                      \
    {                                                                                  \
        uint4 rg[8];                                                                   \
        _Pragma("unroll")                                                              \
        for (int i = 0; i < 4; ++i) {                                                  \
            int e = i*256 + tid; int r = e >> 3, u = e & 7;                            \
            rg[i]   = *(const uint4*)((Ahi) + (size_t)(bm*128 + r)*512 + u*8);         \
            rg[4+i] = *(const uint4*)((Bhi) + (size_t)(lbn*128 + r)*512 + u*8);        \
        }                                                                              \
        _Pragma("unroll")                                                              \
        for (int i = 0; i < 4; ++i) {                                                  \
            int e = i*256 + tid; int r = e >> 3, u = e & 7;                            \
            unsigned off = swz((unsigned)(r*128 + u*16));                              \
            *(uint4*)(smem + off)          = rg[i];                                    \
            *(uint4*)(smem + 16384u + off) = rg[4+i];                                  \
        }                                                                              \
    }                                                                                  \
    __syncthreads();                                                                   \
    for (int c = 0; c < 24; ++c) {                                                     \
        uint4 rn[8];                                                                   \
        if (c < 23) {                                                                  \
            const int cn = c + 1;                                                      \
            const __nv_bfloat16* As = (cn >= 16) ? (Alo) : (Ahi);                      \
            const __nv_bfloat16* Bs = (cn >= 8 && cn < 16) ? (Blo) : (Bhi);            \
            const int kc = cn & 7;                                                     \
            _Pragma("unroll")                                                          \
            for (int i = 0; i < 4; ++i) {                                              \
                int e = i*256 + tid; int r = e >> 3, u = e & 7;                        \
                rn[i]   = *(const uint4*)(As + (size_t)(bm*128 + r)*512 + kc*64 + u*8);\
                rn[4+i] = *(const uint4*)(Bs + (size_t)(lbn*128 + r)*512 + kc*64 + u*8);\
            }                                                                          \
        }                                                                              \
        gemm_compute_stage(sb, c & 1, wm, wn, lane, acc);                              \
        if (c < 23) {                                                                  \
            const unsigned basest = (unsigned)((c + 1) & 1) * 32768u;                  \
            _Pragma("unroll")                                                          \
            for (int i = 0; i < 4; ++i) {                                              \
                int e = i*256 + tid; int r = e >> 3, u = e & 7;                        \
                unsigned off = swz((unsigned)(r*128 + u*16));                          \
                *(uint4*)(smem + basest + off)          = rn[i];                       \
                *(uint4*)(smem + basest + 16384u + off) = rn[4+i];                     \
            }                                                                          \
        }                                                                              \
        __syncthreads();                                                               \
    }                                                                                  \
    _Pragma("unroll")                                                                  \
    for (int ma = 0; ma < 4; ++ma) {                                                   \
        const int row = bm*128 + wm*64 + ma*16 + (lane >> 2);                          \
        _Pragma("unroll")                                                              \
        for (int na = 0; na < 4; ++na) {                                               \
            const int col = lbn*128 + wn*32 + na*8 + (lane & 3)*2;                     \
            const float b0 = (biasptr)[col], b1 = (biasptr)[col+1];                    \
            float2 o0, o1;                                                             \
            o0.x = (alphav)*(acc[ma][na][0] + b0);                                     \
            o0.y = (alphav)*(acc[ma][na][1] + b1);                                     \
            o1.x = (alphav)*(acc[ma][na][2] + b0);                                     \
            o1.y = (alphav)*(acc[ma][na][3] + b1);                                     \
            *(float2*)((Cptr) + (size_t)row*(Nw) + col)     = o0;                      \
            *(float2*)((Cptr) + (size_t)(row+8)*(Nw) + col) = o1;                      \
        }                                                                              \
    }                                                                                  \
}

__device__ __forceinline__ void gemm_compute_stage(
    unsigned sb, int st, int wm, int wn, int lane, float acc[4][4][4])
{
    const unsigned sA = sb + (unsigned)st * 32768u;
    const unsigned sB = sA + 16384u;
    const int la = lane & 15;
    #pragma unroll
    for (int ks = 0; ks < 4; ++ks) {
        unsigned a[4][4], b[4][2];
        #pragma unroll
        for (int ma = 0; ma < 4; ++ma) {
            unsigned arow = (unsigned)(wm*64 + ma*16 + la);
            unsigned ab   = (unsigned)(ks*32 + ((lane>>4)&1)*16);
            ldsm_x4(a[ma], sA + swz(arow*128u + ab));
        }
        #pragma unroll
        for (int na = 0; na < 4; ++na) {
            unsigned brow = (unsigned)(wn*32 + na*8 + (la & 7));
            unsigned bb   = (unsigned)(ks*32 + ((la>>3)&1)*16);
            ldsm_x2(b[na], sB + swz(brow*128u + bb));
        }
        #pragma unroll
        for (int ma = 0; ma < 4; ++ma)
            #pragma unroll
            for (int na = 0; na < 4; ++na)
                mma16816(acc[ma][na], a[ma], b[na]);
    }
}

// generic single GEMM (used for the Wo projection)
__global__ __launch_bounds__(256) void gemm_mma_kernel(
    const __nv_bfloat16* __restrict__ Ahi, const __nv_bfloat16* __restrict__ Alo,
    const __nv_bfloat16* __restrict__ Bhi, const __nv_bfloat16* __restrict__ Blo,
    const float* __restrict__ bias, float* __restrict__ C, int N, float alpha)
{
    extern __shared__ __align__(128) char smem[];
    const unsigned sb = smem_u32(smem);
    const int tid  = threadIdx.x;
    const int lane = tid & 31, wid = tid >> 5;
    const int wm = wid >> 2, wn = wid & 3;
    const int bm = blockIdx.y, lbn = blockIdx.x;
    GEMM_CORE(Ahi, Alo, Bhi, Blo, C, N, alpha, bias);
}

// fused 4-projection GEMM: bn 0-3 Q, 4-7 K, 8-11 V, 12-19 D-logits
__global__ __launch_bounds__(256) void proj4_kernel(
    const __nv_bfloat16* __restrict__ Ahi, const __nv_bfloat16* __restrict__ Alo,
    const __nv_bfloat16* __restrict__ Qh, const __nv_bfloat16* __restrict__ Ql,
    const __nv_bfloat16* __restrict__ Kh, const __nv_bfloat16* __restrict__ Kl,
    const __nv_bfloat16* __restrict__ Vh, const __nv_bfloat16* __restrict__ Vl,
    const __nv_bfloat16* __restrict__ Dh, const __nv_bfloat16* __restrict__ Dlw,
    const float* __restrict__ bq, const float* __restrict__ bk,
    const float* __restrict__ bv, const float* __restrict__ bd,
    float* __restrict__ oQ, float* __restrict__ oK,
    float* __restrict__ oV, float* __restrict__ oD)
{
    extern __shared__ __align__(128) char smem[];
    const unsigned sb = smem_u32(smem);
    const int tid  = threadIdx.x;
    const int lane = tid & 31, wid = tid >> 5;
    const int wm = wid >> 2, wn = wid & 3;
    const int bm = blockIdx.y;
    const int bn = blockIdx.x;

    const __nv_bfloat16 *Bh, *Bl; const float* bias; float* Cp;
    int lbn, N; float alpha = 1.f;
    if (bn < 4)       { lbn = bn;    Bh = Qh; Bl = Ql;  bias = bq; Cp = oQ; N = 512; alpha = 0.125f; }
    else if (bn < 8)  { lbn = bn-4;  Bh = Kh; Bl = Kl;  bias = bk; Cp = oK; N = 512; }
    else if (bn < 12) { lbn = bn-8;  Bh = Vh; Bl = Vl;  bias = bv; Cp = oV; N = 512; }
    else              { lbn = bn-12; Bh = Dh; Bl = Dlw; bias = bd; Cp = oD; N = 1024; }
    GEMM_CORE(Ahi, Alo, Bh, Bl, Cp, N, alpha, bias);
}

// ---------------- LayerNorm over rows of 512, two tensors in one launch ----------------
__global__ __launch_bounds__(128) void ln512x2_kernel(
    float* __restrict__ Y1, float* __restrict__ Y2, int M1,
    const float* __restrict__ gam, const float* __restrict__ bet)
{
    const int row = blockIdx.x;
    float* x = (row < M1) ? (Y1 + (size_t)row * HD) : (Y2 + (size_t)(row - M1) * HD);
    const int t = threadIdx.x;
    float4 v = *(float4*)(x + t*4);
    float s  = v.x+v.y+v.z+v.w;
    float ss = v.x*v.x + v.y*v.y + v.z*v.z + v.w*v.w;
    #pragma unroll
    for (int o=16;o>0;o>>=1) {
        s  += __shfl_xor_sync(0xffffffffu, s, o);
        ss += __shfl_xor_sync(0xffffffffu, ss, o);
    }
    __shared__ float rs[4], rss[4];
    if ((t&31)==0) { rs[t>>5]=s; rss[t>>5]=ss; }
    __syncthreads();
    s  = rs[0]+rs[1]+rs[2]+rs[3];
    ss = rss[0]+rss[1]+rss[2]+rss[3];
    const float mean = s * (1.f/HD);
    const float var  = ss*(1.f/HD) - mean*mean;
    const float inv  = rsqrtf(var + 1e-5f);
    float4 g4 = *(const float4*)(gam + t*4);
    float4 b4 = *(const float4*)(bet + t*4);
    v.x = (v.x-mean)*inv*g4.x + b4.x;
    v.y = (v.y-mean)*inv*g4.y + b4.y;
    v.z = (v.z-mean)*inv*g4.z + b4.z;
    v.w = (v.w-mean)*inv*g4.w + b4.w;
    *(float4*)(x + t*4) = v;
}

// ---------------- softmax over sequence axis of g_Dl: store exp, write 1/sum to g_inv ----------------
__global__ void softmax_seq_kernel()
{
    const int b = blockIdx.y;
    const int j = blockIdx.x*32 + threadIdx.x;
    const int ty = threadIdx.y;
    float m = -3.0e38f;
    for (int s = ty; s < SSEQ; s += 32)
        m = fmaxf(m, g_Dl[(size_t)(b*SSEQ+s)*HL + j]);
    __shared__ float sM[32][33];
    __shared__ float sS[32][33];
    sM[ty][threadIdx.x] = m;
    __syncthreads();
    float M = -3.0e38f;
    #pragma unroll
    for (int i=0;i<32;i++) M = fmaxf(M, sM[i][threadIdx.x]);
    float ssum = 0.f;
    for (int s = ty; s < SSEQ; s += 32) {
        size_t off = (size_t)(b*SSEQ+s)*HL + j;
        float e = __expf(g_Dl[off] - M);
        g_Dl[off] = e;
        ssum += e;
    }
    sS[ty][threadIdx.x] = ssum;
    __syncthreads();
    if (ty == 0) {
        float tot = 0.f;
        #pragma unroll
        for (int i=0;i<32;i++) tot += sS[i][threadIdx.x];
        g_inv[b*HL + j] = 1.f / tot;
    }
}

// ---------------- zero Kc/Vc ----------------
__global__ void zero_kv_kernel()
{
    int i = blockIdx.x*256 + threadIdx.x;
    if (i < BB*LM*HD) { g_Kc[i]=0.f; g_Vc[i]=0.f; }
}

// ---------------- landmark Kc/Vc on HMMA: M=128 landmarks, N=128 (K||V dims), split-K=8 ----------------
// grid (BB*NH, 8), 256 thr. A = hs^T [l][s] hi/lo (16KB each); B = K/V [s][d] hi/lo (8KB each), trans-loaded.
__global__ __launch_bounds__(256) void landmark_mma_kernel()
{
    extern __shared__ __align__(128) char smem[];
    char* Ah  = smem;
    char* Al  = smem + 16384;
    char* KTh = smem + 32768;
    char* KTl = smem + 40960;
    char* VTh = smem + 49152;
    char* VTl = smem + 57344;
    const unsigned sb = smem_u32(smem);

    const int b = blockIdx.x >> 3, h = blockIdx.x & 7;
    const int s0 = blockIdx.y * 512;
    const int t = threadIdx.x;
    const int lane = t & 31, wid = t >> 5;
    const int wm = wid >> 2;          // 0-1: M half
    const int wn = wid & 3;           // 0-1: Kc, 2-3: Vc; (wn&1): d half
    const int la = lane & 15;

    float acc[4][4][4];
    #pragma unroll
    for (int i=0;i<4;i++)
        #pragma unroll
        for (int j=0;j<4;j++)
            #pragma unroll
            for (int k=0;k<4;k++) acc[i][j][k]=0.f;

    for (int ch = 0; ch < 8; ++ch) {
        __syncthreads();
        const int scb = s0 + ch*64;
        // hs^T tile: A[l][sc] (transpose during load; 2B scattered stores, swizzle spreads banks)
        #pragma unroll
        for (int u = 0; u < 8; ++u) {
            int idx = u*256 + t;          // 2048 float4
            int sc = idx >> 5;
            int l  = (idx & 31) * 4;
            float4 v = *(const float4*)&g_Dl[(size_t)(b*SSEQ + scb + sc)*HL + h*LM + l];
            #pragma unroll
            for (int jj = 0; jj < 4; ++jj) {
                float x = (&v.x)[jj];
                __nv_bfloat16 hh, ll; bsplit(x, hh, ll);
                unsigned off = swz((unsigned)((l+jj)*128 + sc*2));
                *(__nv_bfloat16*)(Ah + off) = hh;
                *(__nv_bfloat16*)(Al + off) = ll;
            }
        }
        // K, V tiles [s][d]
        #pragma unroll
        for (int u = 0; u < 4; ++u) {
            int idx = u*256 + t;          // 1024 float4
            int s = idx >> 4, dq = (idx & 15) * 4;
            size_t go = (size_t)(b*SSEQ + scb + s)*HD + h*DHEAD + dq;
            unsigned off = swz((unsigned)(s*128 + dq*2));
            float4 kv = *(const float4*)&g_K[go];
            __nv_bfloat16 h0,h1,h2,h3,l0,l1,l2,l3;
            bsplit(kv.x,h0,l0); bsplit(kv.y,h1,l1); bsplit(kv.z,h2,l2); bsplit(kv.w,h3,l3);
            *(__nv_bfloat162*)(KTh+off)   = __halves2bfloat162(h0,h1);
            *(__nv_bfloat162*)(KTh+off+4) = __halves2bfloat162(h2,h3);
            *(__nv_bfloat162*)(KTl+off)   = __halves2bfloat162(l0,l1);
            *(__nv_bfloat162*)(KTl+off+4) = __halves2bfloat162(l2,l3);
            float4 vv = *(const float4*)&g_V[go];
            bsplit(vv.x,h0,l0); bsplit(vv.y,h1,l1); bsplit(vv.z,h2,l2); bsplit(vv.w,h3,l3);
            *(__nv_bfloat162*)(VTh+off)   = __halves2bfloat162(h0,h1);
            *(__nv_bfloat162*)(VTh+off+4) = __halves2bfloat162(h2,h3);
            *(__nv_bfloat162*)(VTl+off)   = __halves2bfloat162(l0,l1);
            *(__nv_bfloat162*)(VTl+off+4) = __halves2bfloat162(l2,l3);
        }
        __syncthreads();

        const unsigned sAh = sb, sAl = sb + 16384u;
        const unsigned sBh = (wn < 2) ? sb + 32768u : sb + 49152u;
        const unsigned sBl = sBh + 8192u;
        #pragma unroll
        for (int te = 0; te < 3; ++te) {
            const unsigned aB = (te==2) ? sAl : sAh;
            const unsigned bB = (te==1) ? sBl : sBh;
            #pragma unroll
            for (int ks = 0; ks < 4; ++ks) {
                unsigned afr[4][4];
                #pragma unroll
                for (int ma = 0; ma < 4; ++ma)
                    ldsm_x4(afr[ma], aB + swz((unsigned)((wm*64 + ma*16 + la)*128 + ks*32 + ((lane>>4)&1)*16)));
                #pragma unroll
                for (int nf = 0; nf < 4; ++nf) {
                    unsigned bfr[2];
                    ldsm_x2t(bfr, bB + swz((unsigned)((ks*16 + (la&7) + ((la>>3)&1)*8)*128 + ((wn&1)*32 + nf*8)*2)));
                    #pragma unroll
                    for (int ma = 0; ma < 4; ++ma)
                        mma16816(acc[ma][nf], afr[ma], bfr);
                }
            }
        }
    }

    // epilogue: scale by softmax inv (per landmark row), atomicAdd into Kc/Vc
    float* dst = (wn < 2) ? g_Kc : g_Vc;
    #pragma unroll
    for (int ma = 0; ma < 4; ++ma) {
        const int r0 = wm*64 + ma*16 + (lane>>2);
        const float i0 = g_inv[b*HL + h*LM + r0];
        const float i1 = g_inv[b*HL + h*LM + r0 + 8];
        #pragma unroll
        for (int nf = 0; nf < 4; ++nf) {
            const int d0 = (wn&1)*32 + nf*8 + (lane&3)*2;
            size_t o0 = (size_t)(b*LM + r0)*HD + h*DHEAD + d0;
            size_t o1 = (size_t)(b*LM + r0 + 8)*HD + h*DHEAD + d0;
            atomicAdd(&dst[o0],   acc[ma][nf][0]*i0);
            atomicAdd(&dst[o0+1], acc[ma][nf][1]*i0);
            atomicAdd(&dst[o1],   acc[ma][nf][2]*i1);
            atomicAdd(&dst[o1+1], acc[ma][nf][3]*i1);
        }
    }
}

// ---------------- fused attention on HMMA: QK^T + softmax + PV, bf16-split 3-term ----------------
__global__ __launch_bounds__(256) void attn_kernel(
    const int* __restrict__ mask,
    __nv_bfloat16* __restrict__ Chi, __nv_bfloat16* __restrict__ Clo)
{
    extern __shared__ __align__(128) char smem[];
    float* Sc = (float*)smem;
    char* Ph = smem + 49280;
    char* Pl = Ph + 4096;
    char* Th = Pl + 4096;
    char* Tl = Th + 8192;
    __shared__ int vld[64];

    const unsigned sb  = smem_u32(smem);
    const unsigned sPh = sb + 49280u, sPl = sPh + 4096u;
    const unsigned sTh = sPl + 4096u, sTl = sTh + 8192u;

    const int b  = blockIdx.z;
    const int h  = blockIdx.y;
    const int q0 = blockIdx.x * QT;
    const int g  = q0 >> 7;
    const int t  = threadIdx.x;
    const int lane = t & 31, wn = t >> 5;
    const int la = lane & 15;

    // ---- Q (32x64 fp32) -> bf16 hi/lo swizzled smem ----
    #pragma unroll
    for (int u = 0; u < 2; ++u) {
        int idx = u*256 + t;
        int q = idx >> 4, c = idx & 15;
        float4 v = *(const float4*)&g_Q[(size_t)(b*SSEQ+q0+q)*HD + h*DHEAD + c*4];
        __nv_bfloat16 h0,h1,h2,h3,l0,l1,l2,l3;
        bsplit(v.x,h0,l0); bsplit(v.y,h1,l1); bsplit(v.z,h2,l2); bsplit(v.w,h3,l3);
        unsigned off = swz((unsigned)(q*128 + c*8));
        *(__nv_bfloat162*)(Ph+off)   = __halves2bfloat162(h0,h1);
        *(__nv_bfloat162*)(Ph+off+4) = __halves2bfloat162(h2,h3);
        *(__nv_bfloat162*)(Pl+off)   = __halves2bfloat162(l0,l1);
        *(__nv_bfloat162*)(Pl+off+4) = __halves2bfloat162(l2,l3);
    }

    // ---- score tiles ----
    for (int kt = 0; kt < 6; ++kt) {
        __syncthreads();
        if (t < 64) {
            int ok = 1;
            if (kt >= 2) {
                int p = g*WWIN - EXTW + (kt-2)*64 + t;
                ok = (p >= 0 && p < SSEQ) ? (mask[b*SSEQ+p] != 0) : 0;
            }
            vld[t] = ok;
        }
        #pragma unroll
        for (int u = 0; u < 4; ++u) {
            int idx = u*256 + t;
            int kk = idx >> 4, c = idx & 15;
            float4 v = make_float4(0.f,0.f,0.f,0.f);
            if (kt < 2) {
                v = *(const float4*)&g_Kc[(size_t)(b*LM + kt*64 + kk)*HD + h*DHEAD + c*4];
            } else {
                int p = g*WWIN - EXTW + (kt-2)*64 + kk;
                if (p >= 0 && p < SSEQ)
                    v = *(const float4*)&g_K[(size_t)(b*SSEQ+p)*HD + h*DHEAD + c*4];
            }
            __nv_bfloat16 h0,h1,h2,h3,l0,l1,l2,l3;
            bsplit(v.x,h0,l0); bsplit(v.y,h1,l1); bsplit(v.z,h2,l2); bsplit(v.w,h3,l3);
            unsigned off = swz((unsigned)(kk*128 + c*8));
            *(__nv_bfloat162*)(Th+off)   = __halves2bfloat162(h0,h1);
            *(__nv_bfloat162*)(Th+off+4) = __halves2bfloat162(h2,h3);
            *(__nv_bfloat162*)(Tl+off)   = __halves2bfloat162(l0,l1);
            *(__nv_bfloat162*)(Tl+off+4) = __halves2bfloat162(l2,l3);
        }
        __syncthreads();

        float acc[3][2][4];
        #pragma unroll
        for (int te=0;te<3;te++)
            #pragma unroll
            for (int ma=0;ma<2;ma++)
                #pragma unroll
                for (int r=0;r<4;r++) acc[te][ma][r]=0.f;

        #pragma unroll
        for (int te = 0; te < 3; ++te) {
            const unsigned aB = (te==2) ? sPl : sPh;
            const unsigned bB = (te==1) ? sTl : sTh;
            #pragma unroll
            for (int ks = 0; ks < 4; ++ks) {
                unsigned bfr[2];
                ldsm_x2(bfr, bB + swz((unsigned)((wn*8 + (la&7))*128 + ks*32 + ((la>>3)&1)*16)));
                #pragma unroll
                for (int ma = 0; ma < 2; ++ma) {
                    unsigned afr[4];
                    ldsm_x4(afr, aB + swz((unsigned)((ma*16 + la)*128 + ks*32 + ((lane>>4)&1)*16)));
                    mma16816(acc[te][ma], afr, bfr);
                }
            }
        }
        #pragma unroll
        for (int ma = 0; ma < 2; ++ma) {
            const int r0 = ma*16 + (lane>>2);
            const int c0 = wn*8 + (lane&3)*2;
            const int kgl = kt*64 + c0;
            float s00 = acc[0][ma][0]+acc[1][ma][0]+acc[2][ma][0];
            float s01 = acc[0][ma][1]+acc[1][ma][1]+acc[2][ma][1];
            float s10 = acc[0][ma][2]+acc[1][ma][2]+acc[2][ma][2];
            float s11 = acc[0][ma][3]+acc[1][ma][3]+acc[2][ma][3];
            Sc[r0*385 + kgl]       = vld[c0]   ? s00 : -3.0e38f;
            Sc[r0*385 + kgl+1]     = vld[c0+1] ? s01 : -3.0e38f;
            Sc[(r0+8)*385 + kgl]   = vld[c0]   ? s10 : -3.0e38f;
            Sc[(r0+8)*385 + kgl+1] = vld[c0+1] ? s11 : -3.0e38f;
        }
    }
    __syncthreads();

    // ---- softmax over 384 keys (8 lanes per query row) ----
    {
        const int qg = t >> 3;
        const int kb = t & 7;
        float m = -3.0e38f;
        for (int k=kb; k<NKEY; k+=8) m = fmaxf(m, Sc[qg*385+k]);
        #pragma unroll
        for (int o=4;o>0;o>>=1) m = fmaxf(m, __shfl_xor_sync(0xffffffffu, m, o));
        float ssum = 0.f;
        for (int k=kb; k<NKEY; k+=8) {
            float e = __expf(Sc[qg*385+k] - m);
            Sc[qg*385+k] = e;
            ssum += e;
        }
        #pragma unroll
        for (int o=4;o>0;o>>=1) ssum += __shfl_xor_sync(0xffffffffu, ssum, o);
        float inv = (mask[b*SSEQ+q0+qg] != 0) ? (1.f/ssum) : 0.f;
        for (int k=kb; k<NKEY; k+=8) Sc[qg*385+k] *= inv;
    }

    // ---- PV: accumulate over 6 tiles ----
    float accP[3][2][4];
    #pragma unroll
    for (int te=0;te<3;te++)
        #pragma unroll
        for (int ma=0;ma<2;ma++)
            #pragma unroll
            for (int r=0;r<4;r++) accP[te][ma][r]=0.f;

    for (int kt = 0; kt < 6; ++kt) {
        __syncthreads();
        #pragma unroll
        for (int u = 0; u < 4; ++u) {
            int idx = u*256 + t;
            int kk = idx >> 4, c = idx & 15;
            float4 v = make_float4(0.f,0.f,0.f,0.f);
            if (kt < 2) {
                v = *(const float4*)&g_Vc[(size_t)(b*LM + kt*64 + kk)*HD + h*DHEAD + c*4];
            } else {
                int p = g*WWIN - EXTW + (kt-2)*64 + kk;
                if (p >= 0 && p < SSEQ)
                    v = *(const float4*)&g_V[(size_t)(b*SSEQ+p)*HD + h*DHEAD + c*4];
            }
            __nv_bfloat16 h0,h1,h2,h3,l0,l1,l2,l3;
            bsplit(v.x,h0,l0); bsplit(v.y,h1,l1); bsplit(v.z,h2,l2); bsplit(v.w,h3,l3);
            unsigned off = swz((unsigned)(kk*128 + c*8));
            *(__nv_bfloat162*)(Th+off)   = __halves2bfloat162(h0,h1);
            *(__nv_bfloat162*)(Th+off+4) = __halves2bfloat162(h2,h3);
            *(__nv_bfloat162*)(Tl+off)   = __halves2bfloat162(l0,l1);
            *(__nv_bfloat162*)(Tl+off+4) = __halves2bfloat162(l2,l3);
        }
        #pragma unroll
        for (int u = 0; u < 2; ++u) {
            int el = (u*256 + t)*4;
            int q = el >> 6, k = el & 63;
            float p0 = Sc[q*385 + kt*64 + k];
            float p1 = Sc[q*385 + kt*64 + k+1];
            float p2 = Sc[q*385 + kt*64 + k+2];
            float p3 = Sc[q*385 + kt*64 + k+3];
            __nv_bfloat16 h0,h1,h2,h3,l0,l1,l2,l3;
            bsplit(p0,h0,l0); bsplit(p1,h1,l1); bsplit(p2,h2,l2); bsplit(p3,h3,l3);
            unsigned off = swz((unsigned)(q*128 + k*2));
            *(__nv_bfloat162*)(Ph+off)   = __halves2bfloat162(h0,h1);
            *(__nv_bfloat162*)(Ph+off+4) = __halves2bfloat162(h2,h3);
            *(__nv_bfloat162*)(Pl+off)   = __halves2bfloat162(l0,l1);
            *(__nv_bfloat162*)(Pl+off+4) = __halves2bfloat162(l2,l3);
        }
        __syncthreads();

        #pragma unroll
        for (int te = 0; te < 3; ++te) {
            const unsigned aB = (te==2) ? sPl : sPh;
            const unsigned bB = (te==1) ? sTl : sTh;
            #pragma unroll
            for (int ks = 0; ks < 4; ++ks) {
                unsigned bfr[2];
                ldsm_x2t(bfr, bB + swz((unsigned)((ks*16 + (la&7) + ((la>>3)&1)*8)*128 + wn*16)));
                #pragma unroll
                for (int ma = 0; ma < 2; ++ma) {
                    unsigned afr[4];
                    ldsm_x4(afr, aB + swz((unsigned)((ma*16 + la)*128 + ks*32 + ((lane>>4)&1)*16)));
                    mma16816(accP[te][ma], afr, bfr);
                }
            }
        }
    }

    // ---- epilogue: C bf16 hi/lo ----
    #pragma unroll
    for (int ma = 0; ma < 2; ++ma) {
        const int r0 = ma*16 + (lane>>2);
        const int d0 = wn*8 + (lane&3)*2;
        float x00 = accP[0][ma][0]+accP[1][ma][0]+accP[2][ma][0];
        float x01 = accP[0][ma][1]+accP[1][ma][1]+accP[2][ma][1];
        float x10 = accP[0][ma][2]+accP[1][ma][2]+accP[2][ma][2];
        float x11 = accP[0][ma][3]+accP[1][ma][3]+accP[2][ma][3];
        __nv_bfloat16 h0,h1,l0,l1;
        size_t off0 = (size_t)(b*SSEQ + q0 + r0)*HD + h*DHEAD + d0;
        bsplit(x00,h0,l0); bsplit(x01,h1,l1);
        *(__nv_bfloat162*)(Chi + off0) = __halves2bfloat162(h0,h1);
        *(__nv_bfloat162*)(Clo + off0) = __halves2bfloat162(l0,l1);
        size_t off1 = (size_t)(b*SSEQ + q0 + r0 + 8)*HD + h*DHEAD + d0;
        bsplit(x10,h0,l0); bsplit(x11,h1,l1);
        *(__nv_bfloat162*)(Chi + off1) = __halves2bfloat162(h0,h1);
        *(__nv_bfloat162*)(Clo + off1) = __halves2bfloat162(l0,l1);
    }
}

// ---------------- host launcher (single stream) ----------------
extern "C" void kernel_launch(void* const* d_in, const int* in_sizes, int n_in,
                              void* d_out, int out_size)
{
    const float* X    = (const float*)d_in[0];
    const int*   mask = (const int*)  d_in[1];
    const float* Wq   = (const float*)d_in[2];
    const float* bq   = (const float*)d_in[3];
    const float* Wk   = (const float*)d_in[4];
    const float* bk   = (const float*)d_in[5];
    const float* Wv   = (const float*)d_in[6];
    const float* bv   = (const float*)d_in[7];
    const float* Wo   = (const float*)d_in[8];
    const float* bo   = (const float*)d_in[9];
    const float* lnlg = (const float*)d_in[10];
    const float* lnlb = (const float*)d_in[11];
    const float* lnsg = (const float*)d_in[12];
    const float* lnsb = (const float*)d_in[13];
    const float* Wd   = (const float*)d_in[14];
    const float* bd   = (const float*)d_in[15];
    float* out = (float*)d_out;

    float *pQ,*pK,*pV,*pDl,*pKc,*pVc;
    cudaGetSymbolAddress((void**)&pQ,  g_Q);
    cudaGetSymbolAddress((void**)&pK,  g_K);
    cudaGetSymbolAddress((void**)&pV,  g_V);
    cudaGetSymbolAddress((void**)&pDl, g_Dl);
    cudaGetSymbolAddress((void**)&pKc, g_Kc);
    cudaGetSymbolAddress((void**)&pVc, g_Vc);
    __nv_bfloat16* bf;
    cudaGetSymbolAddress((void**)&bf, g_bf);

    static int init_done = 0;
    if (!init_done) {
        cudaFuncSetAttribute(attn_kernel, cudaFuncAttributeMaxDynamicSharedMemorySize, 73856);
        cudaFuncSetAttribute(gemm_mma_kernel, cudaFuncAttributeMaxDynamicSharedMemorySize, 65536);
        cudaFuncSetAttribute(proj4_kernel, cudaFuncAttributeMaxDynamicSharedMemorySize, 65536);
        cudaFuncSetAttribute(landmark_mma_kernel, cudaFuncAttributeMaxDynamicSharedMemorySize, 65536);
        init_done = 1;
    }

    const int M = BB*SSEQ;                       // 8192

    // bf16 splits + all weight transposes
    split_kernel<<<2048,256>>>(X, bf+XHI, bf+XLO, M*HD);
    transpose_split_all_kernel<<<1536,dim3(32,8)>>>(Wq, Wk, Wv, Wd, Wo, bf);

    // fused 4-projection GEMM (Q carries the 1/sqrt(DH) scale)
    proj4_kernel<<<dim3(20,64),256,65536>>>(
        bf+XHI, bf+XLO,
        bf+WQTH, bf+WQTL, bf+WKTH, bf+WKTL, bf+WVTH, bf+WVTL, bf+WDTH, bf+WDTL,
        bq, bk, bv, bd, pQ, pK, pV, pDl);

    // ln_l on K and V in one launch
    ln512x2_kernel<<<2*M,128>>>(pK, pV, M, lnlg, lnlb);

    // hs: exp + per-column inv (normalization folded into landmark epilogue)
    softmax_seq_kernel<<<dim3(HL/32, BB), dim3(32,32)>>>();

    // landmark Kc/Vc on HMMA
    zero_kv_kernel<<<512,256>>>();
    landmark_mma_kernel<<<dim3(BB*NH, 8),256,65536>>>();
    ln512x2_kernel<<<2*BB*LM,128>>>(pKc, pVc, BB*LM, lnsg, lnsb);

    // fused long-short attention on HMMA (writes bf16 hi/lo C directly)
    attn_kernel<<<dim3(SSEQ/QT, NH, BB), 256, 73856>>>(mask, bf+CHI, bf+CLO);

    // output projection on HMMA
    gemm_mma_kernel<<<dim3(4,64),256,65536>>>(bf+CHI, bf+CLO, bf+WOTH, bf+WOTL, bo, out, 512, 1.f);
}